// round 7
// baseline (speedup 1.0000x reference)
#include <cuda_runtime.h>
#include <math.h>

#define B_ 32
#define T_ 256
#define S_ 512
#define H_ 512
#define G_ 2048   // 4*H
#define NB 128    // persistent grid size (must all be co-resident)

// ---------------- scratch: __device__ globals (no allocation allowed) --------
__device__ float g_XG[T_ * B_ * G_];   // [t][b][4H] pre-gated input (64 MB)
__device__ float g_X1[T_ * B_ * H_];   // [t][b][H] layer-0 outputs (16 MB)
__device__ float g_h[B_ * H_];         // recurrent h (h_tilde)
__device__ float g_c[B_ * H_];         // recurrent c
__device__ float g_cat[B_ * 2 * H_];   // [wc | hy] per batch row
__device__ float g_target[B_ * H_];    // hy @ Wa_in
__device__ float g_scores[B_ * S_];    // raw attention scores
__device__ float g_pm[B_ * 32];        // per-chunk max
__device__ float g_pz[B_ * 32];        // per-chunk sumexp
__device__ float g_pwc[B_ * 32 * H_];  // per-chunk weighted-ctx partials (2 MB)

// ---------------- software grid barrier --------------------------------------
__device__ unsigned g_count = 0;
__device__ volatile unsigned g_gen = 0;

__device__ __forceinline__ void gridbar() {
    __syncthreads();
    if (threadIdx.x == 0) {
        __threadfence();
        unsigned gen = g_gen;
        if (atomicAdd(&g_count, 1u) == NB - 1) {
            g_count = 0;
            __threadfence();
            g_gen = gen + 1;
        } else {
            while (g_gen == gen) { }
        }
        __threadfence();
    }
    __syncthreads();
}

// ---------------- precompute XG = x @ Wi + (bi + bh) --------------------------
// M=8192 (m = t*32+b), N=2048, K=512. BM=128, BN=64, BK=16, 256 thr, 8x4 tile.
__global__ void __launch_bounds__(256) k_pre(const float* __restrict__ Xin,
                                             const float* __restrict__ Wi,
                                             const float* __restrict__ bi,
                                             const float* __restrict__ bh,
                                             int layer) {
    __shared__ float As[16][128];
    __shared__ float Bs[16][64];
    const int tid = threadIdx.x;
    const int tx = tid & 15, ty = tid >> 4;
    const int n0 = blockIdx.x * 64, m0 = blockIdx.y * 128;
    const int m_l = tid & 127, kb = (tid >> 7) * 8;
    const int m = m0 + m_l;
    const float* arow;
    if (layer == 0) {
        int bb = m & 31, tt = m >> 5;
        arow = Xin + ((size_t)bb * T_ + tt) * H_;
    } else {
        arow = g_X1 + (size_t)m * H_;
    }
    const int bkk = tid >> 4, bnn = (tid & 15) * 4;

    float acc[8][4];
#pragma unroll
    for (int i = 0; i < 8; i++)
#pragma unroll
        for (int j = 0; j < 4; j++) acc[i][j] = 0.f;

    for (int k0 = 0; k0 < H_; k0 += 16) {
        float4 a0 = *(const float4*)(arow + k0 + kb);
        float4 a1 = *(const float4*)(arow + k0 + kb + 4);
        As[kb + 0][m_l] = a0.x; As[kb + 1][m_l] = a0.y;
        As[kb + 2][m_l] = a0.z; As[kb + 3][m_l] = a0.w;
        As[kb + 4][m_l] = a1.x; As[kb + 5][m_l] = a1.y;
        As[kb + 6][m_l] = a1.z; As[kb + 7][m_l] = a1.w;
        *(float4*)&Bs[bkk][bnn] =
            *(const float4*)(Wi + (size_t)(k0 + bkk) * G_ + n0 + bnn);
        __syncthreads();
#pragma unroll
        for (int kk = 0; kk < 16; kk++) {
            float4 b4  = *(const float4*)&Bs[kk][tx * 4];
            float4 alo = *(const float4*)&As[kk][ty * 8];
            float4 ahi = *(const float4*)&As[kk][ty * 8 + 4];
            float av[8] = {alo.x, alo.y, alo.z, alo.w, ahi.x, ahi.y, ahi.z, ahi.w};
#pragma unroll
            for (int i = 0; i < 8; i++) {
                acc[i][0] = fmaf(av[i], b4.x, acc[i][0]);
                acc[i][1] = fmaf(av[i], b4.y, acc[i][1]);
                acc[i][2] = fmaf(av[i], b4.z, acc[i][2]);
                acc[i][3] = fmaf(av[i], b4.w, acc[i][3]);
            }
        }
        __syncthreads();
    }
    float4 b1 = *(const float4*)(bi + n0 + tx * 4);
    float4 b2 = *(const float4*)(bh + n0 + tx * 4);
    float4 bias = {b1.x + b2.x, b1.y + b2.y, b1.z + b2.z, b1.w + b2.w};
#pragma unroll
    for (int i = 0; i < 8; i++) {
        float4 o = {acc[i][0] + bias.x, acc[i][1] + bias.y,
                    acc[i][2] + bias.z, acc[i][3] + bias.w};
        *(float4*)&g_XG[(size_t)(m0 + ty * 8 + i) * G_ + n0 + tx * 4] = o;
    }
}

// ---------------- persistent per-layer scan kernel -----------------------------
__global__ void __launch_bounds__(256, 1) k_layer(
    const float* __restrict__ ctx,
    const float* __restrict__ Wh,
    const float* __restrict__ Wain,
    const float* __restrict__ Waout,
    const float* __restrict__ h0,
    const float* __restrict__ c0,
    float* __restrict__ outx,
    float* __restrict__ outh,
    float* __restrict__ outc,
    float* __restrict__ outa,
    int layer)
{
    __shared__ float sm[10240];        // 40 KB scratch, reused per phase
    float* red = sm + 8192;            // 2048-float reduction area
    const int blk = blockIdx.x, tid = threadIdx.x;
    const int lane = tid & 31, wrp = tid >> 5;

    for (int t = 0; t < T_; t++) {
        // ===== phase A: gates = XG[t] + h@Wh, fused LSTM elementwise =====
        {
            const int bg = blk >> 5, jg = blk & 31;       // 4 bgroups x 32 jgroups
            const int b0 = bg * 8, j0 = jg * 16;
            const float* hp = (t == 0) ? h0 : g_h;
            for (int i = tid; i < 1024; i += 256)
                ((float4*)sm)[i] = ((const float4*)(hp + b0 * H_))[i];
            __syncthreads();
            const int n_loc = tid & 63;                   // gate*16 + j
            const int gate = n_loc >> 4, jj = n_loc & 15;
            const int ks = tid >> 6;                      // 4 k-splits x 128 k
            const int n = gate * H_ + j0 + jj;
            float acc[8];
#pragma unroll
            for (int i = 0; i < 8; i++) acc[i] = 0.f;
            const float* wp = Wh + (size_t)(ks * 128) * G_ + n;
            const float* hb = sm + ks * 128;
#pragma unroll 16
            for (int k = 0; k < 128; k++) {
                float wv = wp[(size_t)k * G_];
#pragma unroll
                for (int b = 0; b < 8; b++)
                    acc[b] = fmaf(hb[b * 512 + k], wv, acc[b]);
            }
#pragma unroll
            for (int b = 0; b < 8; b++) red[(ks * 64 + n_loc) * 8 + b] = acc[b];
            __syncthreads();
            if (tid < 128) {
                int bb = tid >> 4, j2 = tid & 15;
                int b = b0 + bb, j = j0 + j2;
                float gt[4];
#pragma unroll
                for (int g = 0; g < 4; g++) {
                    int nl = g * 16 + j2;
                    float v = red[nl * 8 + bb] + red[(64 + nl) * 8 + bb]
                            + red[(128 + nl) * 8 + bb] + red[(192 + nl) * 8 + bb];
                    gt[g] = v + g_XG[(size_t)(t * B_ + b) * G_ + g * H_ + j];
                }
                float cold = (t == 0) ? c0[b * H_ + j] : g_c[b * H_ + j];
                float ig = 1.f / (1.f + expf(-gt[0]));
                float fg = 1.f / (1.f + expf(-gt[1]));
                float gg = tanhf(gt[2]);
                float og = 1.f / (1.f + expf(-gt[3]));
                float cy = fg * cold + ig * gg;
                float hy = og * tanhf(cy);
                g_c[b * H_ + j] = cy;
                g_cat[b * 2 * H_ + H_ + j] = hy;          // hy half of concat
            }
        }
        gridbar();

        // ===== phase B: target = hy @ Wa_in =====
        {
            const int bg = blk >> 5, ng = blk & 31;
            const int b0 = bg * 8, n0 = ng * 16;
            for (int i = tid; i < 1024; i += 256) {
                int bb = i >> 7, f = i & 127;
                ((float4*)sm)[bb * 128 + f] =
                    ((const float4*)(g_cat + (b0 + bb) * 1024 + 512))[f];
            }
            __syncthreads();
            const int n_loc = tid & 15, ks = tid >> 4;    // 16 splits x 32 k
            float acc[8];
#pragma unroll
            for (int i = 0; i < 8; i++) acc[i] = 0.f;
            const float* wp = Wain + (size_t)(ks * 32) * H_ + n0 + n_loc;
            const float* hb = sm + ks * 32;
#pragma unroll 16
            for (int k = 0; k < 32; k++) {
                float wv = wp[(size_t)k * H_];
#pragma unroll
                for (int b = 0; b < 8; b++)
                    acc[b] = fmaf(hb[b * 512 + k], wv, acc[b]);
            }
#pragma unroll
            for (int b = 0; b < 8; b++) red[(ks * 16 + n_loc) * 8 + b] = acc[b];
            __syncthreads();
            if (tid < 128) {
                int bb = tid >> 4, nn = tid & 15;
                float v = 0.f;
#pragma unroll
                for (int s2 = 0; s2 < 16; s2++) v += red[(s2 * 16 + nn) * 8 + bb];
                g_target[(b0 + bb) * H_ + n0 + nn] = v;
            }
        }
        gridbar();

        // ===== phase C: attention — one-pass online softmax per 16-s chunk =====
        {
            const int b = blk >> 2;
            const int ch = (blk & 3) * 8 + wrp;           // 32 chunks of 16 s
            const int s0 = ch * 16;
            const float4* tp = (const float4*)(g_target + b * H_);
            float4 tg0 = tp[lane], tg1 = tp[32 + lane];
            float4 tg2 = tp[64 + lane], tg3 = tp[96 + lane];
            float m = -3.4e38f, z = 0.f;
            float4 a0 = {0,0,0,0}, a1 = a0, a2 = a0, a3 = a0;
            for (int i = 0; i < 16; i++) {
                int s = s0 + i;
                const float4* cr = (const float4*)(ctx + ((size_t)s * B_ + b) * H_);
                float4 c0v = cr[lane],      c1v = cr[32 + lane];
                float4 c2v = cr[64 + lane], c3v = cr[96 + lane];
                float p = c0v.x * tg0.x + c0v.y * tg0.y + c0v.z * tg0.z + c0v.w * tg0.w
                        + c1v.x * tg1.x + c1v.y * tg1.y + c1v.z * tg1.z + c1v.w * tg1.w
                        + c2v.x * tg2.x + c2v.y * tg2.y + c2v.z * tg2.z + c2v.w * tg2.w
                        + c3v.x * tg3.x + c3v.y * tg3.y + c3v.z * tg3.z + c3v.w * tg3.w;
#pragma unroll
                for (int o = 16; o; o >>= 1) p += __shfl_xor_sync(0xffffffffu, p, o);
                if (!lane) g_scores[b * S_ + s] = p;
                float mn = fmaxf(m, p);
                float sc = expf(m - mn);
                float e  = expf(p - mn);
                z = z * sc + e;
                a0.x = a0.x * sc + e * c0v.x; a0.y = a0.y * sc + e * c0v.y;
                a0.z = a0.z * sc + e * c0v.z; a0.w = a0.w * sc + e * c0v.w;
                a1.x = a1.x * sc + e * c1v.x; a1.y = a1.y * sc + e * c1v.y;
                a1.z = a1.z * sc + e * c1v.z; a1.w = a1.w * sc + e * c1v.w;
                a2.x = a2.x * sc + e * c2v.x; a2.y = a2.y * sc + e * c2v.y;
                a2.z = a2.z * sc + e * c2v.z; a2.w = a2.w * sc + e * c2v.w;
                a3.x = a3.x * sc + e * c3v.x; a3.y = a3.y * sc + e * c3v.y;
                a3.z = a3.z * sc + e * c3v.z; a3.w = a3.w * sc + e * c3v.w;
                m = mn;
            }
            if (!lane) { g_pm[b * 32 + ch] = m; g_pz[b * 32 + ch] = z; }
            float4* pw = (float4*)(g_pwc + ((size_t)b * 32 + ch) * H_);
            pw[lane] = a0; pw[32 + lane] = a1; pw[64 + lane] = a2; pw[96 + lane] = a3;
        }
        gridbar();

        // ===== phase D: combine chunks -> wc, attention-output scatter =====
        {
            const int b = blk >> 2, q = blk & 3;
            const int k0 = q * 128;
            if (wrp == 0) {
                float mv = g_pm[b * 32 + lane];
                float zv = g_pz[b * 32 + lane];
                float M = mv;
#pragma unroll
                for (int o = 16; o; o >>= 1) M = fmaxf(M, __shfl_xor_sync(0xffffffffu, M, o));
                float zz = zv * expf(mv - M);
                float Z = zz;
#pragma unroll
                for (int o = 16; o; o >>= 1) Z += __shfl_xor_sync(0xffffffffu, Z, o);
                sm[lane] = expf(mv - M) / Z;
                if (!lane) { sm[32] = M; sm[33] = 1.f / Z; }
            }
            __syncthreads();
            const int kk = tid & 127, half = tid >> 7;
            float v = 0.f;
            const float* pwb = g_pwc + ((size_t)b * 32 + half * 16) * H_ + k0 + kk;
#pragma unroll
            for (int c = 0; c < 16; c++)
                v = fmaf(sm[half * 16 + c], pwb[(size_t)c * H_], v);
            sm[64 + tid] = v;
            __syncthreads();
            if (half == 0) {
                g_cat[b * 2 * H_ + k0 + kk] = sm[64 + tid] + sm[64 + tid + 128];
            } else if (outa) {
                int s = k0 + kk;
                outa[(size_t)s * (T_ * B_) + t * B_ + b] =
                    expf(g_scores[b * S_ + s] - sm[32]) * sm[33];
            }
        }
        gridbar();

        // ===== phase E: h = tanh([wc|hy] @ Wa_out), outputs =====
        {
            const int bg = blk >> 5, ng = blk & 31;
            const int b0 = bg * 8, n0 = ng * 16;
            for (int i = tid; i < 2048; i += 256)
                ((float4*)sm)[i] = ((const float4*)(g_cat + b0 * 1024))[i];
            __syncthreads();
            const int n_loc = tid & 15, ks = tid >> 4;    // 16 splits x 64 k
            float acc[8];
#pragma unroll
            for (int i = 0; i < 8; i++) acc[i] = 0.f;
            const float* wp = Waout + (size_t)(ks * 64) * H_ + n0 + n_loc;
            const float* ib = sm + ks * 64;
#pragma unroll 16
            for (int k = 0; k < 64; k++) {
                float wv = wp[(size_t)k * H_];
#pragma unroll
                for (int b = 0; b < 8; b++)
                    acc[b] = fmaf(ib[b * 1024 + k], wv, acc[b]);
            }
#pragma unroll
            for (int b = 0; b < 8; b++) red[(ks * 16 + n_loc) * 8 + b] = acc[b];
            __syncthreads();
            if (tid < 128) {
                int bb = tid >> 4, nn = tid & 15;
                float v = 0.f;
#pragma unroll
                for (int s2 = 0; s2 < 16; s2++) v += red[(s2 * 16 + nn) * 8 + bb];
                v = tanhf(v);
                int b = b0 + bb, n = n0 + nn;
                g_h[b * H_ + n] = v;
                if (layer == 0)
                    g_X1[((size_t)t * B_ + b) * H_ + n] = v;
                else
                    outx[(size_t)b * (T_ * H_) + (size_t)t * H_ + n] = v;
                if (t == T_ - 1) {
                    outh[b * H_ + n] = v;
                    outc[b * H_ + n] = g_c[b * H_ + n];
                }
            }
        }
        gridbar();
    }
}

// ---------------- host orchestration ------------------------------------------
extern "C" void kernel_launch(void* const* d_in, const int* in_sizes, int n_in,
                              void* d_out, int out_size) {
    const float* input = (const float*)d_in[0];
    const float* h0    = (const float*)d_in[1];
    const float* c0    = (const float*)d_in[2];
    const float* ctx   = (const float*)d_in[3];
    const float* Wi    = (const float*)d_in[4];
    const float* bi    = (const float*)d_in[5];
    const float* Wh    = (const float*)d_in[6];
    const float* bh    = (const float*)d_in[7];
    const float* Wain  = (const float*)d_in[8];
    const float* Waout = (const float*)d_in[9];

    float* out  = (float*)d_out;
    float* outx = out;                                   // (B,T,H)
    float* outh = out  + (size_t)B_ * T_ * H_;           // (2,B,H)
    float* outc = outh + 2 * B_ * H_;                    // (2,B,H)
    float* outa = outc + 2 * B_ * H_;                    // (S, T*B)

    for (int l = 0; l < 2; l++) {
        const float* Wi_l    = Wi    + (size_t)l * H_ * G_;
        const float* bi_l    = bi    + l * G_;
        const float* Wh_l    = Wh    + (size_t)l * H_ * G_;
        const float* bh_l    = bh    + l * G_;
        const float* Wain_l  = Wain  + (size_t)l * H_ * H_;
        const float* Waout_l = Waout + (size_t)l * 2 * H_ * H_;

        k_pre<<<dim3(G_ / 64, (T_ * B_) / 128), 256>>>(input, Wi_l, bi_l, bh_l, l);
        k_layer<<<NB, 256>>>(ctx, Wh_l, Wain_l, Waout_l, h0, c0,
                             outx, outh + l * B_ * H_, outc + l * B_ * H_,
                             l == 1 ? outa : nullptr, l);
    }
}

// round 8
// speedup vs baseline: 1.2184x; 1.2184x over previous
#include <cuda_runtime.h>
#include <math.h>

#define B_ 32
#define T_ 256
#define S_ 512
#define H_ 512
#define G_ 2048   // 4*H
#define NB 128
#define NT 512

// ---------------- scratch: __device__ globals ---------------------------------
__device__ float g_XG[T_ * B_ * G_];   // [t][b][4H] pre-gated input (64 MB)
__device__ float g_X1[T_ * B_ * H_];   // [t][b][H] layer-0 outputs (16 MB)
__device__ float g_h[B_ * H_];
__device__ float g_c[B_ * H_];
__device__ float g_cat[B_ * 2 * H_];   // [wc | hy]
__device__ float g_target[B_ * H_];
__device__ float g_pm[B_ * 4];         // per-block-part max
__device__ float g_pz[B_ * 4];         // per-block-part sumexp
__device__ float g_pwc[B_ * 4 * H_];   // per-block-part weighted-ctx partials
__device__ float g_M[T_ * B_];         // final softmax max per (t,b), layer 1
__device__ float g_iZ[T_ * B_];        // 1/Z per (t,b), layer 1

// ---------------- fence-free grid barrier -------------------------------------
__device__ unsigned g_count = 0;
__device__ unsigned g_count2 = 0;
__device__ unsigned g_gen = 0;

__device__ __forceinline__ unsigned atom_add_acqrel(unsigned* p, unsigned v) {
    unsigned old;
    asm volatile("atom.add.acq_rel.gpu.u32 %0, [%1], %2;"
                 : "=r"(old) : "l"(p), "r"(v) : "memory");
    return old;
}
__device__ __forceinline__ unsigned ld_acq(unsigned* p) {
    unsigned v;
    asm volatile("ld.acquire.gpu.u32 %0, [%1];" : "=r"(v) : "l"(p) : "memory");
    return v;
}
__device__ __forceinline__ void st_rel(unsigned* p, unsigned v) {
    asm volatile("st.release.gpu.u32 [%0], %1;" :: "l"(p), "r"(v) : "memory");
}
__device__ __forceinline__ void gridbar(unsigned target) {
    __syncthreads();
    if (threadIdx.x == 0) {
        unsigned old = atom_add_acqrel(&g_count, 1u);
        if (old == NB - 1) {
            g_count = 0;                 // ordered before release below
            st_rel(&g_gen, target);
        } else {
            while (ld_acq(&g_gen) != target) { }
        }
    }
    __syncthreads();
}

// ---------------- precompute XG = x @ Wi + (bi + bh) --------------------------
__global__ void __launch_bounds__(256) k_pre(const float* __restrict__ Xin,
                                             const float* __restrict__ Wi,
                                             const float* __restrict__ bi,
                                             const float* __restrict__ bh,
                                             int layer) {
    __shared__ float As[16][128];
    __shared__ float Bs[16][64];
    const int tid = threadIdx.x;
    const int tx = tid & 15, ty = tid >> 4;
    const int n0 = blockIdx.x * 64, m0 = blockIdx.y * 128;
    const int m_l = tid & 127, kb = (tid >> 7) * 8;
    const int m = m0 + m_l;
    const float* arow;
    if (layer == 0) {
        int bb = m & 31, tt = m >> 5;
        arow = Xin + ((size_t)bb * T_ + tt) * H_;
    } else {
        arow = g_X1 + (size_t)m * H_;
    }
    const int bkk = tid >> 4, bnn = (tid & 15) * 4;

    float acc[8][4];
#pragma unroll
    for (int i = 0; i < 8; i++)
#pragma unroll
        for (int j = 0; j < 4; j++) acc[i][j] = 0.f;

    for (int k0 = 0; k0 < H_; k0 += 16) {
        float4 a0 = *(const float4*)(arow + k0 + kb);
        float4 a1 = *(const float4*)(arow + k0 + kb + 4);
        As[kb + 0][m_l] = a0.x; As[kb + 1][m_l] = a0.y;
        As[kb + 2][m_l] = a0.z; As[kb + 3][m_l] = a0.w;
        As[kb + 4][m_l] = a1.x; As[kb + 5][m_l] = a1.y;
        As[kb + 6][m_l] = a1.z; As[kb + 7][m_l] = a1.w;
        *(float4*)&Bs[bkk][bnn] =
            *(const float4*)(Wi + (size_t)(k0 + bkk) * G_ + n0 + bnn);
        __syncthreads();
#pragma unroll
        for (int kk = 0; kk < 16; kk++) {
            float4 b4  = *(const float4*)&Bs[kk][tx * 4];
            float4 alo = *(const float4*)&As[kk][ty * 8];
            float4 ahi = *(const float4*)&As[kk][ty * 8 + 4];
            float av[8] = {alo.x, alo.y, alo.z, alo.w, ahi.x, ahi.y, ahi.z, ahi.w};
#pragma unroll
            for (int i = 0; i < 8; i++) {
                acc[i][0] = fmaf(av[i], b4.x, acc[i][0]);
                acc[i][1] = fmaf(av[i], b4.y, acc[i][1]);
                acc[i][2] = fmaf(av[i], b4.z, acc[i][2]);
                acc[i][3] = fmaf(av[i], b4.w, acc[i][3]);
            }
        }
        __syncthreads();
    }
    float4 b1 = *(const float4*)(bi + n0 + tx * 4);
    float4 b2 = *(const float4*)(bh + n0 + tx * 4);
    float4 bias = {b1.x + b2.x, b1.y + b2.y, b1.z + b2.z, b1.w + b2.w};
#pragma unroll
    for (int i = 0; i < 8; i++) {
        float4 o = {acc[i][0] + bias.x, acc[i][1] + bias.y,
                    acc[i][2] + bias.z, acc[i][3] + bias.w};
        *(float4*)&g_XG[(size_t)(m0 + ty * 8 + i) * G_ + n0 + tx * 4] = o;
    }
}

// ---------------- persistent per-layer scan kernel ----------------------------
// dyn smem: [0,8192) tile, [8192,12288) red, [12288,53248) ctx cache (80 rows)
__global__ void __launch_bounds__(NT, 1) k_layer(
    const float* __restrict__ ctx,
    const float* __restrict__ Wh,
    const float* __restrict__ Wain,
    const float* __restrict__ Waout,
    const float* __restrict__ h0,
    const float* __restrict__ c0,
    float* __restrict__ outx,
    float* __restrict__ outh,
    float* __restrict__ outc,
    float* __restrict__ outa,
    int layer)
{
    extern __shared__ float sm[];
    float* red  = sm + 8192;
    float* ctxc = sm + 12288;
    const int blk = blockIdx.x, tid = threadIdx.x;
    const int lane = tid & 31, wrp = tid >> 5;

    // ---- one-time ctx cache preload: this block's b, 5 of 8 rows per warp ----
    {
        const int b = blk >> 2, q = blk & 3;
        const int sbase = q * 128;
        for (int idx = tid; idx < 10240; idx += NT) {   // 80 rows x 128 float4
            int r = idx >> 7, c4 = idx & 127;
            int w2 = r / 5, i2 = r % 5;
            int s = sbase + w2 * 8 + i2;
            ((float4*)ctxc)[idx] =
                ((const float4*)(ctx + ((size_t)s * B_ + b) * H_))[c4];
        }
        __syncthreads();
    }

    for (int t = 0; t < T_; t++) {
        const unsigned t5 = (unsigned)t * 5;

        // ===== A: gates = XG[t] + h@Wh, fused LSTM elementwise =====
        {
            const int bg = blk >> 5, jg = blk & 31;
            const int b0 = bg * 8, j0 = jg * 16;
            const float* hp = (t == 0) ? h0 : g_h;
            for (int i = tid; i < 1024; i += NT)
                ((float4*)sm)[i] = ((const float4*)(hp + b0 * H_))[i];
            __syncthreads();
            const int n_loc = tid & 63;
            const int gate = n_loc >> 4, jj = n_loc & 15;
            const int ks = tid >> 6;                   // 8 splits x 64 k
            const int n = gate * H_ + j0 + jj;
            float acc[8];
#pragma unroll
            for (int i = 0; i < 8; i++) acc[i] = 0.f;
            const float* wp = Wh + (size_t)(ks * 64) * G_ + n;
            const float* hb = sm + ks * 64;
#pragma unroll 4
            for (int k4 = 0; k4 < 16; k4++) {
                float w0 = wp[(size_t)(k4 * 4 + 0) * G_];
                float w1 = wp[(size_t)(k4 * 4 + 1) * G_];
                float w2 = wp[(size_t)(k4 * 4 + 2) * G_];
                float w3 = wp[(size_t)(k4 * 4 + 3) * G_];
#pragma unroll
                for (int b = 0; b < 8; b++) {
                    float4 h4 = ((const float4*)(hb + b * 512))[k4];
                    acc[b] = fmaf(h4.x, w0, fmaf(h4.y, w1,
                             fmaf(h4.z, w2, fmaf(h4.w, w3, acc[b]))));
                }
            }
#pragma unroll
            for (int b = 0; b < 8; b++) red[(ks * 64 + n_loc) * 8 + b] = acc[b];
            __syncthreads();
            {   // 512 threads: one gate value each
                int bb = tid >> 6, g2 = (tid >> 4) & 3, j2 = tid & 15;
                int nl = g2 * 16 + j2;
                float v = 0.f;
#pragma unroll
                for (int s2 = 0; s2 < 8; s2++) v += red[(s2 * 64 + nl) * 8 + bb];
                v += g_XG[(size_t)(t * B_ + b0 + bb) * G_ + g2 * H_ + j0 + j2];
                sm[4096 + tid] = v;                    // sg[bb][g2][j2]
            }
            __syncthreads();
            if (tid < 128) {
                int bb = tid >> 4, j2 = tid & 15;
                float gi = sm[4096 + bb * 64 + j2];
                float gf = sm[4096 + bb * 64 + 16 + j2];
                float gg = sm[4096 + bb * 64 + 32 + j2];
                float go = sm[4096 + bb * 64 + 48 + j2];
                int b = b0 + bb, j = j0 + j2;
                float cold = (t == 0) ? c0[b * H_ + j] : g_c[b * H_ + j];
                float ig = 1.f / (1.f + expf(-gi));
                float fg = 1.f / (1.f + expf(-gf));
                float g2v = tanhf(gg);
                float og = 1.f / (1.f + expf(-go));
                float cy = fg * cold + ig * g2v;
                float hy = og * tanhf(cy);
                g_c[b * H_ + j] = cy;
                g_cat[b * 2 * H_ + H_ + j] = hy;
            }
        }
        gridbar(t5 + 1);

        // ===== B: target = hy @ Wa_in =====
        {
            const int bg = blk >> 5, ng = blk & 31;
            const int b0 = bg * 8, n0 = ng * 16;
            for (int i = tid; i < 1024; i += NT) {
                int bb = i >> 7, f = i & 127;
                ((float4*)sm)[i] = ((const float4*)(g_cat + (b0 + bb) * 1024 + 512))[f];
            }
            __syncthreads();
            const int n_loc = tid & 15, ks = tid >> 4;  // 32 splits x 16 k
            float acc[8];
#pragma unroll
            for (int i = 0; i < 8; i++) acc[i] = 0.f;
            const float* wp = Wain + (size_t)(ks * 16) * H_ + n0 + n_loc;
            const float* hb = sm + ks * 16;
#pragma unroll
            for (int k4 = 0; k4 < 4; k4++) {
                float w0 = wp[(size_t)(k4 * 4 + 0) * H_];
                float w1 = wp[(size_t)(k4 * 4 + 1) * H_];
                float w2 = wp[(size_t)(k4 * 4 + 2) * H_];
                float w3 = wp[(size_t)(k4 * 4 + 3) * H_];
#pragma unroll
                for (int b = 0; b < 8; b++) {
                    float4 h4 = ((const float4*)(hb + b * 512))[k4];
                    acc[b] = fmaf(h4.x, w0, fmaf(h4.y, w1,
                             fmaf(h4.z, w2, fmaf(h4.w, w3, acc[b]))));
                }
            }
#pragma unroll
            for (int b = 0; b < 8; b++) red[(ks * 16 + n_loc) * 8 + b] = acc[b];
            __syncthreads();
            if (tid < 128) {
                int bb = tid >> 4, nn = tid & 15;
                float v = 0.f;
#pragma unroll
                for (int s2 = 0; s2 < 32; s2++) v += red[(s2 * 16 + nn) * 8 + bb];
                g_target[(b0 + bb) * H_ + n0 + nn] = v;
            }
        }
        gridbar(t5 + 2);

        // ===== C: attention — online softmax, 8 s-rows per warp, 5 cached ====
        {
            const int b = blk >> 2, q = blk & 3;
            const int sbase = q * 128;
            const float4* tp = (const float4*)(g_target + b * H_);
            float4 tg0 = tp[lane],      tg1 = tp[32 + lane];
            float4 tg2 = tp[64 + lane], tg3 = tp[96 + lane];
            float m = -3.4e38f, z = 0.f;
            float4 a0 = {0,0,0,0}, a1 = a0, a2 = a0, a3 = a0;
#pragma unroll
            for (int i = 0; i < 8; i++) {
                int s = sbase + wrp * 8 + i;
                float4 c0v, c1v, c2v, c3v;
                if (i < 5) {
                    const float4* cc = (const float4*)(ctxc + (wrp * 5 + i) * 512);
                    c0v = cc[lane];      c1v = cc[32 + lane];
                    c2v = cc[64 + lane]; c3v = cc[96 + lane];
                } else {
                    const float4* cr = (const float4*)(ctx + ((size_t)s * B_ + b) * H_);
                    c0v = cr[lane];      c1v = cr[32 + lane];
                    c2v = cr[64 + lane]; c3v = cr[96 + lane];
                }
                float p = c0v.x * tg0.x + c0v.y * tg0.y + c0v.z * tg0.z + c0v.w * tg0.w
                        + c1v.x * tg1.x + c1v.y * tg1.y + c1v.z * tg1.z + c1v.w * tg1.w
                        + c2v.x * tg2.x + c2v.y * tg2.y + c2v.z * tg2.z + c2v.w * tg2.w
                        + c3v.x * tg3.x + c3v.y * tg3.y + c3v.z * tg3.z + c3v.w * tg3.w;
#pragma unroll
                for (int o = 16; o; o >>= 1) p += __shfl_xor_sync(0xffffffffu, p, o);
                if (!lane && outa)
                    outa[(size_t)s * (T_ * B_) + t * B_ + b] = p;   // raw score
                float mn = fmaxf(m, p);
                float sc = expf(m - mn);
                float e  = expf(p - mn);
                z = z * sc + e;
                a0.x = a0.x * sc + e * c0v.x; a0.y = a0.y * sc + e * c0v.y;
                a0.z = a0.z * sc + e * c0v.z; a0.w = a0.w * sc + e * c0v.w;
                a1.x = a1.x * sc + e * c1v.x; a1.y = a1.y * sc + e * c1v.y;
                a1.z = a1.z * sc + e * c1v.z; a1.w = a1.w * sc + e * c1v.w;
                a2.x = a2.x * sc + e * c2v.x; a2.y = a2.y * sc + e * c2v.y;
                a2.z = a2.z * sc + e * c2v.z; a2.w = a2.w * sc + e * c2v.w;
                a3.x = a3.x * sc + e * c3v.x; a3.y = a3.y * sc + e * c3v.y;
                a3.z = a3.z * sc + e * c3v.z; a3.w = a3.w * sc + e * c3v.w;
                m = mn;
            }
            // block-level combine of 16 warp partials
            if (!lane) { red[wrp] = m; red[16 + wrp] = z; }
            __syncthreads();
            if (wrp == 0) {
                float mw = (lane < 16) ? red[lane] : -3.4e38f;
                float zw = (lane < 16) ? red[16 + lane] : 0.f;
                float M = mw;
#pragma unroll
                for (int o = 16; o; o >>= 1)
                    M = fmaxf(M, __shfl_xor_sync(0xffffffffu, M, o));
                float cw = expf(mw - M);
                float Zb = zw * cw;
#pragma unroll
                for (int o = 16; o; o >>= 1) Zb += __shfl_xor_sync(0xffffffffu, Zb, o);
                if (lane < 16) red[32 + lane] = cw;
                if (!lane) { g_pm[b * 4 + q] = M; g_pz[b * 4 + q] = Zb; }
            }
            __syncthreads();
            float cw = red[32 + wrp];
            float4* wp4 = (float4*)(sm + wrp * 512);
            float4 s0v = {a0.x*cw, a0.y*cw, a0.z*cw, a0.w*cw};
            float4 s1v = {a1.x*cw, a1.y*cw, a1.z*cw, a1.w*cw};
            float4 s2v = {a2.x*cw, a2.y*cw, a2.z*cw, a2.w*cw};
            float4 s3v = {a3.x*cw, a3.y*cw, a3.z*cw, a3.w*cw};
            wp4[lane] = s0v; wp4[32 + lane] = s1v;
            wp4[64 + lane] = s2v; wp4[96 + lane] = s3v;
            __syncthreads();
            {
                float v = 0.f;
#pragma unroll
                for (int w2 = 0; w2 < 16; w2++) v += sm[w2 * 512 + tid];
                g_pwc[((size_t)b * 4 + q) * H_ + tid] = v;
            }
        }
        gridbar(t5 + 3);

        // ===== D: combine 4 block-parts -> wc =====
        {
            const int b = blk >> 2, q = blk & 3;
            const int k0 = q * 128;
            if (wrp == 0) {
                float M4 = (lane < 4) ? g_pm[b * 4 + lane] : -3.4e38f;
                float Z4 = (lane < 4) ? g_pz[b * 4 + lane] : 0.f;
                float M = M4;
#pragma unroll
                for (int o = 16; o; o >>= 1)
                    M = fmaxf(M, __shfl_xor_sync(0xffffffffu, M, o));
                float cc = expf(M4 - M);
                float Z = Z4 * cc;
#pragma unroll
                for (int o = 16; o; o >>= 1) Z += __shfl_xor_sync(0xffffffffu, Z, o);
                if (lane < 4) red[lane] = cc;
                if (!lane) {
                    red[4] = 1.f / Z;
                    if (outa) { g_M[t * B_ + b] = M; g_iZ[t * B_ + b] = 1.f / Z; }
                }
            }
            __syncthreads();
            if (tid < 128) {
                int k = k0 + tid;
                float iZ = red[4];
                float v = 0.f;
#pragma unroll
                for (int c2 = 0; c2 < 4; c2++)
                    v += red[c2] * g_pwc[((size_t)b * 4 + c2) * H_ + k];
                g_cat[b * 2 * H_ + k] = v * iZ;
            }
        }
        gridbar(t5 + 4);

        // ===== E: h = tanh([wc|hy] @ Wa_out), outputs =====
        {
            const int bg = blk >> 5, ng = blk & 31;
            const int b0 = bg * 8, n0 = ng * 16;
            for (int i = tid; i < 2048; i += NT)
                ((float4*)sm)[i] = ((const float4*)(g_cat + b0 * 1024))[i];
            __syncthreads();
            const int n_loc = tid & 15, ks = tid >> 4;  // 32 splits x 32 k
            float acc[8];
#pragma unroll
            for (int i = 0; i < 8; i++) acc[i] = 0.f;
            const float* wp = Waout + (size_t)(ks * 32) * H_ + n0 + n_loc;
            const float* ib = sm + ks * 32;
#pragma unroll 4
            for (int k4 = 0; k4 < 8; k4++) {
                float w0 = wp[(size_t)(k4 * 4 + 0) * H_];
                float w1 = wp[(size_t)(k4 * 4 + 1) * H_];
                float w2 = wp[(size_t)(k4 * 4 + 2) * H_];
                float w3 = wp[(size_t)(k4 * 4 + 3) * H_];
#pragma unroll
                for (int b = 0; b < 8; b++) {
                    float4 h4 = ((const float4*)(ib + b * 1024))[k4];
                    acc[b] = fmaf(h4.x, w0, fmaf(h4.y, w1,
                             fmaf(h4.z, w2, fmaf(h4.w, w3, acc[b]))));
                }
            }
#pragma unroll
            for (int b = 0; b < 8; b++) red[(ks * 16 + n_loc) * 8 + b] = acc[b];
            __syncthreads();
            if (tid < 128) {
                int bb = tid >> 4, nn = tid & 15;
                float v = 0.f;
#pragma unroll
                for (int s2 = 0; s2 < 32; s2++) v += red[(s2 * 16 + nn) * 8 + bb];
                v = tanhf(v);
                int b = b0 + bb, n = n0 + nn;
                g_h[b * H_ + n] = v;
                if (layer == 0)
                    g_X1[((size_t)t * B_ + b) * H_ + n] = v;
                else
                    outx[(size_t)b * (T_ * H_) + (size_t)t * H_ + n] = v;
                if (t == T_ - 1) {
                    outh[b * H_ + n] = v;
                    outc[b * H_ + n] = g_c[b * H_ + n];
                }
            }
        }
        gridbar(t5 + 5);
    }

    // reset barrier state for next launch (no one polls after this)
    if (tid == 0) {
        unsigned old = atom_add_acqrel(&g_count2, 1u);
        if (old == NB - 1) {
            g_count2 = 0;
            st_rel(&g_gen, 0u);
        }
    }
}

// ---------------- finalize attention output: in-place softmax ------------------
__global__ void __launch_bounds__(256) k_att(float* __restrict__ outa) {
    const int s = blockIdx.x;
    for (int i = threadIdx.x; i < T_ * B_; i += 256) {
        float v = outa[(size_t)s * (T_ * B_) + i];
        outa[(size_t)s * (T_ * B_) + i] = expf(v - g_M[i]) * g_iZ[i];
    }
}

// ---------------- host orchestration ------------------------------------------
extern "C" void kernel_launch(void* const* d_in, const int* in_sizes, int n_in,
                              void* d_out, int out_size) {
    const float* input = (const float*)d_in[0];
    const float* h0    = (const float*)d_in[1];
    const float* c0    = (const float*)d_in[2];
    const float* ctx   = (const float*)d_in[3];
    const float* Wi    = (const float*)d_in[4];
    const float* bi    = (const float*)d_in[5];
    const float* Wh    = (const float*)d_in[6];
    const float* bh    = (const float*)d_in[7];
    const float* Wain  = (const float*)d_in[8];
    const float* Waout = (const float*)d_in[9];

    float* out  = (float*)d_out;
    float* outx = out;                                   // (B,T,H)
    float* outh = out  + (size_t)B_ * T_ * H_;           // (2,B,H)
    float* outc = outh + 2 * B_ * H_;                    // (2,B,H)
    float* outa = outc + 2 * B_ * H_;                    // (S, T*B)

    const int SMEM = 53248 * 4;  // 208 KB
    cudaFuncSetAttribute(k_layer, cudaFuncAttributeMaxDynamicSharedMemorySize, SMEM);

    for (int l = 0; l < 2; l++) {
        const float* Wi_l    = Wi    + (size_t)l * H_ * G_;
        const float* bi_l    = bi    + l * G_;
        const float* Wh_l    = Wh    + (size_t)l * H_ * G_;
        const float* bh_l    = bh    + l * G_;
        const float* Wain_l  = Wain  + (size_t)l * H_ * H_;
        const float* Waout_l = Waout + (size_t)l * 2 * H_ * H_;

        k_pre<<<dim3(G_ / 64, (T_ * B_) / 128), 256>>>(input, Wi_l, bi_l, bh_l, l);
        k_layer<<<NB, NT, SMEM>>>(ctx, Wh_l, Wain_l, Waout_l, h0, c0,
                                  outx, outh + l * B_ * H_, outc + l * B_ * H_,
                                  l == 1 ? outa : nullptr, l);
    }
    k_att<<<S_, 256>>>(outa);
}

// round 9
// speedup vs baseline: 1.2299x; 1.0095x over previous
#include <cuda_runtime.h>
#include <math.h>

#define B_ 32
#define T_ 256
#define S_ 512
#define H_ 512
#define G_ 2048   // 4*H
#define NB 128
#define NT 512
#define GSZ 32    // blocks per group
#define NGRP 4    // independent groups; each owns 8 batch rows

// ---------------- scratch: __device__ globals ---------------------------------
__device__ float g_XG[T_ * B_ * G_];   // [t][b][4H] pre-gated input (64 MB)
__device__ float g_X1[T_ * B_ * H_];   // [t][b][H] layer-0 outputs (16 MB)
__device__ float g_h[B_ * H_];
__device__ float g_c[B_ * H_];
__device__ float g_cat[B_ * 2 * H_];   // [wc | hy]
__device__ float g_target[B_ * H_];
__device__ float g_pm[B_ * 4];         // per-(b,q) max
__device__ float g_pz[B_ * 4];         // per-(b,q) sumexp
__device__ float g_pwc[B_ * 4 * H_];   // per-(b,q) weighted-ctx partials
__device__ float g_M[T_ * B_];         // final softmax max per (t,b), layer 1
__device__ float g_iZ[T_ * B_];        // 1/Z per (t,b), layer 1

// ---------------- barrier state ------------------------------------------------
__device__ unsigned g_gcnt[NGRP];
__device__ unsigned g_ggen[NGRP];
__device__ unsigned g_grst[NGRP];
__device__ unsigned g_bcnt[B_];        // per-b minisync counters (monotonic)

__device__ __forceinline__ unsigned atom_add_acqrel(unsigned* p, unsigned v) {
    unsigned old;
    asm volatile("atom.add.acq_rel.gpu.u32 %0, [%1], %2;"
                 : "=r"(old) : "l"(p), "r"(v) : "memory");
    return old;
}
__device__ __forceinline__ unsigned ld_acq(unsigned* p) {
    unsigned v;
    asm volatile("ld.acquire.gpu.u32 %0, [%1];" : "=r"(v) : "l"(p) : "memory");
    return v;
}
__device__ __forceinline__ void st_rel(unsigned* p, unsigned v) {
    asm volatile("st.release.gpu.u32 [%0], %1;" :: "l"(p), "r"(v) : "memory");
}
__device__ __forceinline__ void gbar(int gid, unsigned target) {
    __syncthreads();
    if (threadIdx.x == 0) {
        unsigned old = atom_add_acqrel(&g_gcnt[gid], 1u);
        if (old == GSZ - 1) {
            g_gcnt[gid] = 0;
            st_rel(&g_ggen[gid], target);
        } else {
            while (ld_acq(&g_ggen[gid]) != target) { }
        }
    }
    __syncthreads();
}

// ---------------- precompute XG = x @ Wi + (bi + bh) --------------------------
__global__ void __launch_bounds__(256) k_pre(const float* __restrict__ Xin,
                                             const float* __restrict__ Wi,
                                             const float* __restrict__ bi,
                                             const float* __restrict__ bh,
                                             int layer) {
    __shared__ float As[16][128];
    __shared__ float Bs[16][64];
    const int tid = threadIdx.x;
    const int tx = tid & 15, ty = tid >> 4;
    const int n0 = blockIdx.x * 64, m0 = blockIdx.y * 128;
    const int m_l = tid & 127, kb = (tid >> 7) * 8;
    const int m = m0 + m_l;
    const float* arow;
    if (layer == 0) {
        int bb = m & 31, tt = m >> 5;
        arow = Xin + ((size_t)bb * T_ + tt) * H_;
    } else {
        arow = g_X1 + (size_t)m * H_;
    }
    const int bkk = tid >> 4, bnn = (tid & 15) * 4;

    float acc[8][4];
#pragma unroll
    for (int i = 0; i < 8; i++)
#pragma unroll
        for (int j = 0; j < 4; j++) acc[i][j] = 0.f;

    for (int k0 = 0; k0 < H_; k0 += 16) {
        float4 a0 = *(const float4*)(arow + k0 + kb);
        float4 a1 = *(const float4*)(arow + k0 + kb + 4);
        As[kb + 0][m_l] = a0.x; As[kb + 1][m_l] = a0.y;
        As[kb + 2][m_l] = a0.z; As[kb + 3][m_l] = a0.w;
        As[kb + 4][m_l] = a1.x; As[kb + 5][m_l] = a1.y;
        As[kb + 6][m_l] = a1.z; As[kb + 7][m_l] = a1.w;
        *(float4*)&Bs[bkk][bnn] =
            *(const float4*)(Wi + (size_t)(k0 + bkk) * G_ + n0 + bnn);
        __syncthreads();
#pragma unroll
        for (int kk = 0; kk < 16; kk++) {
            float4 b4  = *(const float4*)&Bs[kk][tx * 4];
            float4 alo = *(const float4*)&As[kk][ty * 8];
            float4 ahi = *(const float4*)&As[kk][ty * 8 + 4];
            float av[8] = {alo.x, alo.y, alo.z, alo.w, ahi.x, ahi.y, ahi.z, ahi.w};
#pragma unroll
            for (int i = 0; i < 8; i++) {
                acc[i][0] = fmaf(av[i], b4.x, acc[i][0]);
                acc[i][1] = fmaf(av[i], b4.y, acc[i][1]);
                acc[i][2] = fmaf(av[i], b4.z, acc[i][2]);
                acc[i][3] = fmaf(av[i], b4.w, acc[i][3]);
            }
        }
        __syncthreads();
    }
    float4 b1 = *(const float4*)(bi + n0 + tx * 4);
    float4 b2 = *(const float4*)(bh + n0 + tx * 4);
    float4 bias = {b1.x + b2.x, b1.y + b2.y, b1.z + b2.z, b1.w + b2.w};
#pragma unroll
    for (int i = 0; i < 8; i++) {
        float4 o = {acc[i][0] + bias.x, acc[i][1] + bias.y,
                    acc[i][2] + bias.z, acc[i][3] + bias.w};
        *(float4*)&g_XG[(size_t)(m0 + ty * 8 + i) * G_ + n0 + tx * 4] = o;
    }
}

// ---------------- persistent per-layer scan kernel ----------------------------
// dyn smem: [0,8192) tile, [8192,12288) red, [12288,53248) ctx cache (80 rows)
__global__ void __launch_bounds__(NT, 1) k_layer(
    const float* __restrict__ ctx,
    const float* __restrict__ Wh,
    const float* __restrict__ Wain,
    const float* __restrict__ Waout,
    const float* __restrict__ h0,
    const float* __restrict__ c0,
    float* __restrict__ outx,
    float* __restrict__ outh,
    float* __restrict__ outc,
    float* __restrict__ outa,
    int layer)
{
    extern __shared__ float sm[];
    float* red  = sm + 8192;
    float* ctxc = sm + 12288;
    const int blk = blockIdx.x, tid = threadIdx.x;
    const int lane = tid & 31, wrp = tid >> 5;
    const int gid = blk >> 5, gblk = blk & 31;   // group, rank in group
    const int b0g = gid * 8;                     // this group's batch rows

    const int bC = b0g + (gblk >> 2), qC = gblk & 3;   // phase C/D mapping

    // ---- one-time ctx cache preload: rows for (bC,qC), 5 of 8 per warp ----
    {
        const int sbase = qC * 128;
        for (int idx = tid; idx < 10240; idx += NT) {   // 80 rows x 128 float4
            int r = idx >> 7, c4 = idx & 127;
            int w2 = r / 5, i2 = r % 5;
            int s = sbase + w2 * 8 + i2;
            ((float4*)ctxc)[idx] =
                ((const float4*)(ctx + ((size_t)s * B_ + bC) * H_))[c4];
        }
        __syncthreads();
    }

    for (int t = 0; t < T_; t++) {
        const unsigned t4 = (unsigned)t * 4;

        // ===== A: gates = XG[t] + h@Wh, fused LSTM elementwise =====
        {
            const int j0 = gblk * 16;
            const float* hp = (t == 0) ? h0 : g_h;
            for (int i = tid; i < 1024; i += NT)
                ((float4*)sm)[i] = ((const float4*)(hp + b0g * H_))[i];
            __syncthreads();
            const int n_loc = tid & 63;
            const int gate = n_loc >> 4, jj = n_loc & 15;
            const int ks = tid >> 6;                   // 8 splits x 64 k
            const int n = gate * H_ + j0 + jj;
            float acc[8];
#pragma unroll
            for (int i = 0; i < 8; i++) acc[i] = 0.f;
            const float* wp = Wh + (size_t)(ks * 64) * G_ + n;
            const float* hb = sm + ks * 64;
#pragma unroll 4
            for (int k4 = 0; k4 < 16; k4++) {
                float w0 = wp[(size_t)(k4 * 4 + 0) * G_];
                float w1 = wp[(size_t)(k4 * 4 + 1) * G_];
                float w2 = wp[(size_t)(k4 * 4 + 2) * G_];
                float w3 = wp[(size_t)(k4 * 4 + 3) * G_];
#pragma unroll
                for (int b = 0; b < 8; b++) {
                    float4 h4 = ((const float4*)(hb + b * 512))[k4];
                    acc[b] = fmaf(h4.x, w0, fmaf(h4.y, w1,
                             fmaf(h4.z, w2, fmaf(h4.w, w3, acc[b]))));
                }
            }
#pragma unroll
            for (int b = 0; b < 8; b++) red[(ks * 64 + n_loc) * 8 + b] = acc[b];
            __syncthreads();
            {   // 512 threads: one gate value each
                int bb = tid >> 6, g2 = (tid >> 4) & 3, j2 = tid & 15;
                int nl = g2 * 16 + j2;
                float v = 0.f;
#pragma unroll
                for (int s2 = 0; s2 < 8; s2++) v += red[(s2 * 64 + nl) * 8 + bb];
                v += g_XG[(size_t)(t * B_ + b0g + bb) * G_ + g2 * H_ + j0 + j2];
                sm[4096 + tid] = v;                    // sg[bb][g2][j2]
            }
            __syncthreads();
            if (tid < 128) {
                int bb = tid >> 4, j2 = tid & 15;
                float gi = sm[4096 + bb * 64 + j2];
                float gf = sm[4096 + bb * 64 + 16 + j2];
                float gg = sm[4096 + bb * 64 + 32 + j2];
                float go = sm[4096 + bb * 64 + 48 + j2];
                int b = b0g + bb, j = j0 + j2;
                float cold = (t == 0) ? c0[b * H_ + j] : g_c[b * H_ + j];
                float ig = 1.f / (1.f + expf(-gi));
                float fg = 1.f / (1.f + expf(-gf));
                float g2v = tanhf(gg);
                float og = 1.f / (1.f + expf(-go));
                float cy = fg * cold + ig * g2v;
                float hy = og * tanhf(cy);
                g_c[b * H_ + j] = cy;
                g_cat[b * 2 * H_ + H_ + j] = hy;
            }
        }
        gbar(gid, t4 + 1);

        // ===== B: target = hy @ Wa_in =====
        {
            const int n0 = gblk * 16;
            for (int i = tid; i < 1024; i += NT) {
                int bb = i >> 7, f = i & 127;
                ((float4*)sm)[i] = ((const float4*)(g_cat + (b0g + bb) * 1024 + 512))[f];
            }
            __syncthreads();
            const int n_loc = tid & 15, ks = tid >> 4;  // 32 splits x 16 k
            float acc[8];
#pragma unroll
            for (int i = 0; i < 8; i++) acc[i] = 0.f;
            const float* wp = Wain + (size_t)(ks * 16) * H_ + n0 + n_loc;
            const float* hb = sm + ks * 16;
#pragma unroll
            for (int k4 = 0; k4 < 4; k4++) {
                float w0 = wp[(size_t)(k4 * 4 + 0) * H_];
                float w1 = wp[(size_t)(k4 * 4 + 1) * H_];
                float w2 = wp[(size_t)(k4 * 4 + 2) * H_];
                float w3 = wp[(size_t)(k4 * 4 + 3) * H_];
#pragma unroll
                for (int b = 0; b < 8; b++) {
                    float4 h4 = ((const float4*)(hb + b * 512))[k4];
                    acc[b] = fmaf(h4.x, w0, fmaf(h4.y, w1,
                             fmaf(h4.z, w2, fmaf(h4.w, w3, acc[b]))));
                }
            }
#pragma unroll
            for (int b = 0; b < 8; b++) red[(ks * 16 + n_loc) * 8 + b] = acc[b];
            __syncthreads();
            if (tid < 128) {
                int bb = tid >> 4, nn = tid & 15;
                float v = 0.f;
#pragma unroll
                for (int s2 = 0; s2 < 32; s2++) v += red[(s2 * 16 + nn) * 8 + bb];
                g_target[(b0g + bb) * H_ + n0 + nn] = v;
            }
        }
        gbar(gid, t4 + 2);

        // ===== C: attention — online softmax, 8 s-rows per warp, 5 cached ====
        {
            const int b = bC, q = qC;
            const int sbase = q * 128;
            const float4* tp = (const float4*)(g_target + b * H_);
            float4 tg0 = tp[lane],      tg1 = tp[32 + lane];
            float4 tg2 = tp[64 + lane], tg3 = tp[96 + lane];
            float m = -3.4e38f, z = 0.f;
            float4 a0 = {0,0,0,0}, a1 = a0, a2 = a0, a3 = a0;
#pragma unroll
            for (int i = 0; i < 8; i++) {
                int s = sbase + wrp * 8 + i;
                float4 c0v, c1v, c2v, c3v;
                if (i < 5) {
                    const float4* cc = (const float4*)(ctxc + (wrp * 5 + i) * 512);
                    c0v = cc[lane];      c1v = cc[32 + lane];
                    c2v = cc[64 + lane]; c3v = cc[96 + lane];
                } else {
                    const float4* cr = (const float4*)(ctx + ((size_t)s * B_ + b) * H_);
                    c0v = cr[lane];      c1v = cr[32 + lane];
                    c2v = cr[64 + lane]; c3v = cr[96 + lane];
                }
                float p = c0v.x * tg0.x + c0v.y * tg0.y + c0v.z * tg0.z + c0v.w * tg0.w
                        + c1v.x * tg1.x + c1v.y * tg1.y + c1v.z * tg1.z + c1v.w * tg1.w
                        + c2v.x * tg2.x + c2v.y * tg2.y + c2v.z * tg2.z + c2v.w * tg2.w
                        + c3v.x * tg3.x + c3v.y * tg3.y + c3v.z * tg3.z + c3v.w * tg3.w;
#pragma unroll
                for (int o = 16; o; o >>= 1) p += __shfl_xor_sync(0xffffffffu, p, o);
                if (!lane && outa)
                    outa[(size_t)s * (T_ * B_) + t * B_ + b] = p;   // raw score
                float mn = fmaxf(m, p);
                float sc = expf(m - mn);
                float e  = expf(p - mn);
                z = z * sc + e;
                a0.x = a0.x * sc + e * c0v.x; a0.y = a0.y * sc + e * c0v.y;
                a0.z = a0.z * sc + e * c0v.z; a0.w = a0.w * sc + e * c0v.w;
                a1.x = a1.x * sc + e * c1v.x; a1.y = a1.y * sc + e * c1v.y;
                a1.z = a1.z * sc + e * c1v.z; a1.w = a1.w * sc + e * c1v.w;
                a2.x = a2.x * sc + e * c2v.x; a2.y = a2.y * sc + e * c2v.y;
                a2.z = a2.z * sc + e * c2v.z; a2.w = a2.w * sc + e * c2v.w;
                a3.x = a3.x * sc + e * c3v.x; a3.y = a3.y * sc + e * c3v.y;
                a3.z = a3.z * sc + e * c3v.z; a3.w = a3.w * sc + e * c3v.w;
                m = mn;
            }
            // block-level combine of 16 warp partials
            if (!lane) { red[wrp] = m; red[16 + wrp] = z; }
            __syncthreads();
            if (wrp == 0) {
                float mw = (lane < 16) ? red[lane] : -3.4e38f;
                float zw = (lane < 16) ? red[16 + lane] : 0.f;
                float M = mw;
#pragma unroll
                for (int o = 16; o; o >>= 1)
                    M = fmaxf(M, __shfl_xor_sync(0xffffffffu, M, o));
                float cw = expf(mw - M);
                float Zb = zw * cw;
#pragma unroll
                for (int o = 16; o; o >>= 1) Zb += __shfl_xor_sync(0xffffffffu, Zb, o);
                if (lane < 16) red[32 + lane] = cw;
                if (!lane) { g_pm[b * 4 + q] = M; g_pz[b * 4 + q] = Zb; }
            }
            __syncthreads();
            float cw = red[32 + wrp];
            float4* wp4 = (float4*)(sm + wrp * 512);
            float4 s0v = {a0.x*cw, a0.y*cw, a0.z*cw, a0.w*cw};
            float4 s1v = {a1.x*cw, a1.y*cw, a1.z*cw, a1.w*cw};
            float4 s2v = {a2.x*cw, a2.y*cw, a2.z*cw, a2.w*cw};
            float4 s3v = {a3.x*cw, a3.y*cw, a3.z*cw, a3.w*cw};
            wp4[lane] = s0v; wp4[32 + lane] = s1v;
            wp4[64 + lane] = s2v; wp4[96 + lane] = s3v;
            __syncthreads();
            {
                float v = 0.f;
#pragma unroll
                for (int w2 = 0; w2 < 16; w2++) v += sm[w2 * 512 + tid];
                g_pwc[((size_t)b * 4 + q) * H_ + tid] = v;
            }
            __syncthreads();
            if (tid == 0) atom_add_acqrel(&g_bcnt[b], 1u);   // minisync arrive
        }

        // ===== D: wait 4 partials of b, combine -> wc (fused, no group bar) ===
        {
            const int b = bC, q = qC;
            const int k0 = q * 128;
            if (tid == 0) {
                unsigned tgt = 4u * (unsigned)(t + 1);
                while (ld_acq(&g_bcnt[b]) < tgt) { }
            }
            __syncthreads();
            if (wrp == 0) {
                float M4 = (lane < 4) ? g_pm[b * 4 + lane] : -3.4e38f;
                float Z4 = (lane < 4) ? g_pz[b * 4 + lane] : 0.f;
                float M = M4;
#pragma unroll
                for (int o = 16; o; o >>= 1)
                    M = fmaxf(M, __shfl_xor_sync(0xffffffffu, M, o));
                float cc = expf(M4 - M);
                float Z = Z4 * cc;
#pragma unroll
                for (int o = 16; o; o >>= 1) Z += __shfl_xor_sync(0xffffffffu, Z, o);
                if (lane < 4) red[lane] = cc;
                if (!lane) {
                    red[4] = 1.f / Z;
                    if (outa) { g_M[t * B_ + b] = M; g_iZ[t * B_ + b] = 1.f / Z; }
                }
            }
            __syncthreads();
            if (tid < 128) {
                int k = k0 + tid;
                float iZ = red[4];
                float v = 0.f;
#pragma unroll
                for (int c2 = 0; c2 < 4; c2++)
                    v += red[c2] * g_pwc[((size_t)b * 4 + c2) * H_ + k];
                g_cat[b * 2 * H_ + k] = v * iZ;
            }
        }
        gbar(gid, t4 + 3);

        // ===== E: h = tanh([wc|hy] @ Wa_out), outputs =====
        {
            const int n0 = gblk * 16;
            for (int i = tid; i < 2048; i += NT)
                ((float4*)sm)[i] = ((const float4*)(g_cat + b0g * 1024))[i];
            __syncthreads();
            const int n_loc = tid & 15, ks = tid >> 4;  // 32 splits x 32 k
            float acc[8];
#pragma unroll
            for (int i = 0; i < 8; i++) acc[i] = 0.f;
            const float* wp = Waout + (size_t)(ks * 32) * H_ + n0 + n_loc;
            const float* ib = sm + ks * 32;
#pragma unroll 4
            for (int k4 = 0; k4 < 8; k4++) {
                float w0 = wp[(size_t)(k4 * 4 + 0) * H_];
                float w1 = wp[(size_t)(k4 * 4 + 1) * H_];
                float w2 = wp[(size_t)(k4 * 4 + 2) * H_];
                float w3 = wp[(size_t)(k4 * 4 + 3) * H_];
#pragma unroll
                for (int b = 0; b < 8; b++) {
                    float4 h4 = ((const float4*)(ib + b * 1024))[k4];
                    acc[b] = fmaf(h4.x, w0, fmaf(h4.y, w1,
                             fmaf(h4.z, w2, fmaf(h4.w, w3, acc[b]))));
                }
            }
#pragma unroll
            for (int b = 0; b < 8; b++) red[(ks * 16 + n_loc) * 8 + b] = acc[b];
            __syncthreads();
            if (tid < 128) {
                int bb = tid >> 4, nn = tid & 15;
                float v = 0.f;
#pragma unroll
                for (int s2 = 0; s2 < 32; s2++) v += red[(s2 * 16 + nn) * 8 + bb];
                v = tanhf(v);
                int b = b0g + bb, n = n0 + nn;
                g_h[b * H_ + n] = v;
                if (layer == 0)
                    g_X1[((size_t)t * B_ + b) * H_ + n] = v;
                else
                    outx[(size_t)b * (T_ * H_) + (size_t)t * H_ + n] = v;
                if (t == T_ - 1) {
                    outh[b * H_ + n] = v;
                    outc[b * H_ + n] = g_c[b * H_ + n];
                }
            }
        }
        gbar(gid, t4 + 4);
    }

    // reset group barrier + minisync state for the next launch
    if (tid == 0) {
        unsigned old = atom_add_acqrel(&g_grst[gid], 1u);
        if (old == GSZ - 1) {
            g_grst[gid] = 0;
#pragma unroll
            for (int i = 0; i < 8; i++) g_bcnt[b0g + i] = 0;
            st_rel(&g_ggen[gid], 0u);
        }
    }
}

// ---------------- finalize attention output: in-place softmax ------------------
__global__ void __launch_bounds__(256) k_att(float* __restrict__ outa) {
    const int s = blockIdx.x;
    for (int i = threadIdx.x; i < T_ * B_; i += 256) {
        float v = outa[(size_t)s * (T_ * B_) + i];
        outa[(size_t)s * (T_ * B_) + i] = expf(v - g_M[i]) * g_iZ[i];
    }
}

// ---------------- host orchestration ------------------------------------------
extern "C" void kernel_launch(void* const* d_in, const int* in_sizes, int n_in,
                              void* d_out, int out_size) {
    const float* input = (const float*)d_in[0];
    const float* h0    = (const float*)d_in[1];
    const float* c0    = (const float*)d_in[2];
    const float* ctx   = (const float*)d_in[3];
    const float* Wi    = (const float*)d_in[4];
    const float* bi    = (const float*)d_in[5];
    const float* Wh    = (const float*)d_in[6];
    const float* bh    = (const float*)d_in[7];
    const float* Wain  = (const float*)d_in[8];
    const float* Waout = (const float*)d_in[9];

    float* out  = (float*)d_out;
    float* outx = out;                                   // (B,T,H)
    float* outh = out  + (size_t)B_ * T_ * H_;           // (2,B,H)
    float* outc = outh + 2 * B_ * H_;                    // (2,B,H)
    float* outa = outc + 2 * B_ * H_;                    // (S, T*B)

    const int SMEM = 53248 * 4;  // 208 KB
    cudaFuncSetAttribute(k_layer, cudaFuncAttributeMaxDynamicSharedMemorySize, SMEM);

    for (int l = 0; l < 2; l++) {
        const float* Wi_l    = Wi    + (size_t)l * H_ * G_;
        const float* bi_l    = bi    + l * G_;
        const float* Wh_l    = Wh    + (size_t)l * H_ * G_;
        const float* bh_l    = bh    + l * G_;
        const float* Wain_l  = Wain  + (size_t)l * H_ * H_;
        const float* Waout_l = Waout + (size_t)l * 2 * H_ * H_;

        k_pre<<<dim3(G_ / 64, (T_ * B_) / 128), 256>>>(input, Wi_l, bi_l, bh_l, l);
        k_layer<<<NB, NT, SMEM>>>(ctx, Wh_l, Wain_l, Waout_l, h0, c0,
                                  outx, outh + l * B_ * H_, outc + l * B_ * H_,
                                  l == 1 ? outa : nullptr, l);
    }
    k_att<<<S_, 256>>>(outa);
}

// round 10
// speedup vs baseline: 1.3231x; 1.0758x over previous
#include <cuda_runtime.h>
#include <math.h>

#define B_ 32
#define T_ 256
#define S_ 512
#define H_ 512
#define G_ 2048   // 4*H
#define NB 128
#define NT 512
#define GSZ 32    // blocks per group
#define NGRP 4    // independent groups; each owns 8 batch rows

// smem layout (floats): [0,32768) Wh slice, [32768,49152) Waout slice,
// [49152,57344) scratch (stage/red overlay), [57344,57408) small
#define SW_O 32768
#define SCR  49152
#define SML  57344
#define SMEM_FLOATS 57408

// ---------------- scratch: __device__ globals ---------------------------------
__device__ float g_XG[T_ * B_ * G_];   // [t][b][4H] pre-gated input (64 MB)
__device__ float g_X1[T_ * B_ * H_];   // [t][b][H] layer-0 outputs (16 MB)
__device__ float g_h[B_ * H_];
__device__ float g_c[B_ * H_];
__device__ float g_cat[B_ * 2 * H_];   // [wc | hy]
__device__ float g_target[B_ * H_];
__device__ float g_pm[B_ * 4];         // per-(b,q) max
__device__ float g_pz[B_ * 4];         // per-(b,q) sumexp
__device__ float g_pwc[B_ * 4 * H_];   // per-(b,q) weighted-ctx partials
__device__ float g_M[T_ * B_];         // final softmax max per (t,b), layer 1
__device__ float g_iZ[T_ * B_];        // 1/Z per (t,b), layer 1

// ---------------- barrier state ------------------------------------------------
__device__ unsigned g_gcnt[NGRP];
__device__ unsigned g_ggen[NGRP];
__device__ unsigned g_grst[NGRP];
__device__ unsigned g_bcnt[B_];        // per-b minisync counters (monotonic)

__device__ __forceinline__ unsigned atom_add_acqrel(unsigned* p, unsigned v) {
    unsigned old;
    asm volatile("atom.add.acq_rel.gpu.u32 %0, [%1], %2;"
                 : "=r"(old) : "l"(p), "r"(v) : "memory");
    return old;
}
__device__ __forceinline__ unsigned ld_acq(unsigned* p) {
    unsigned v;
    asm volatile("ld.acquire.gpu.u32 %0, [%1];" : "=r"(v) : "l"(p) : "memory");
    return v;
}
__device__ __forceinline__ void st_rel(unsigned* p, unsigned v) {
    asm volatile("st.release.gpu.u32 [%0], %1;" :: "l"(p), "r"(v) : "memory");
}
__device__ __forceinline__ void gbar(int gid, unsigned target) {
    __syncthreads();
    if (threadIdx.x == 0) {
        unsigned old = atom_add_acqrel(&g_gcnt[gid], 1u);
        if (old == GSZ - 1) {
            g_gcnt[gid] = 0;
            st_rel(&g_ggen[gid], target);
        } else {
            while (ld_acq(&g_ggen[gid]) != target) { }
        }
    }
    __syncthreads();
}

// ---------------- precompute XG = x @ Wi + (bi + bh) --------------------------
__global__ void __launch_bounds__(256) k_pre(const float* __restrict__ Xin,
                                             const float* __restrict__ Wi,
                                             const float* __restrict__ bi,
                                             const float* __restrict__ bh,
                                             int layer) {
    __shared__ float As[16][128];
    __shared__ float Bs[16][64];
    const int tid = threadIdx.x;
    const int tx = tid & 15, ty = tid >> 4;
    const int n0 = blockIdx.x * 64, m0 = blockIdx.y * 128;
    const int m_l = tid & 127, kb = (tid >> 7) * 8;
    const int m = m0 + m_l;
    const float* arow;
    if (layer == 0) {
        int bb = m & 31, tt = m >> 5;
        arow = Xin + ((size_t)bb * T_ + tt) * H_;
    } else {
        arow = g_X1 + (size_t)m * H_;
    }
    const int bkk = tid >> 4, bnn = (tid & 15) * 4;

    float acc[8][4];
#pragma unroll
    for (int i = 0; i < 8; i++)
#pragma unroll
        for (int j = 0; j < 4; j++) acc[i][j] = 0.f;

    for (int k0 = 0; k0 < H_; k0 += 16) {
        float4 a0 = *(const float4*)(arow + k0 + kb);
        float4 a1 = *(const float4*)(arow + k0 + kb + 4);
        As[kb + 0][m_l] = a0.x; As[kb + 1][m_l] = a0.y;
        As[kb + 2][m_l] = a0.z; As[kb + 3][m_l] = a0.w;
        As[kb + 4][m_l] = a1.x; As[kb + 5][m_l] = a1.y;
        As[kb + 6][m_l] = a1.z; As[kb + 7][m_l] = a1.w;
        *(float4*)&Bs[bkk][bnn] =
            *(const float4*)(Wi + (size_t)(k0 + bkk) * G_ + n0 + bnn);
        __syncthreads();
#pragma unroll
        for (int kk = 0; kk < 16; kk++) {
            float4 b4  = *(const float4*)&Bs[kk][tx * 4];
            float4 alo = *(const float4*)&As[kk][ty * 8];
            float4 ahi = *(const float4*)&As[kk][ty * 8 + 4];
            float av[8] = {alo.x, alo.y, alo.z, alo.w, ahi.x, ahi.y, ahi.z, ahi.w};
#pragma unroll
            for (int i = 0; i < 8; i++) {
                acc[i][0] = fmaf(av[i], b4.x, acc[i][0]);
                acc[i][1] = fmaf(av[i], b4.y, acc[i][1]);
                acc[i][2] = fmaf(av[i], b4.z, acc[i][2]);
                acc[i][3] = fmaf(av[i], b4.w, acc[i][3]);
            }
        }
        __syncthreads();
    }
    float4 b1 = *(const float4*)(bi + n0 + tx * 4);
    float4 b2 = *(const float4*)(bh + n0 + tx * 4);
    float4 bias = {b1.x + b2.x, b1.y + b2.y, b1.z + b2.z, b1.w + b2.w};
#pragma unroll
    for (int i = 0; i < 8; i++) {
        float4 o = {acc[i][0] + bias.x, acc[i][1] + bias.y,
                    acc[i][2] + bias.z, acc[i][3] + bias.w};
        *(float4*)&g_XG[(size_t)(m0 + ty * 8 + i) * G_ + n0 + tx * 4] = o;
    }
}

// ---------------- persistent per-layer scan kernel ----------------------------
__global__ void __launch_bounds__(NT, 1) k_layer(
    const float* __restrict__ ctx,
    const float* __restrict__ Wh,
    const float* __restrict__ Wain,
    const float* __restrict__ Waout,
    const float* __restrict__ h0,
    const float* __restrict__ c0,
    float* __restrict__ outx,
    float* __restrict__ outh,
    float* __restrict__ outc,
    float* __restrict__ outa,
    int layer)
{
    extern __shared__ float sm[];
    float* smW = sm;               // Wh slice [kg 0..127][nl 0..63] x float4
    float* smO = sm + SW_O;        // Waout slice [kg 0..255][nl 0..15] x float4
    float* scr = sm + SCR;         // 8192-float stage/red overlay
    float* sml = sm + SML;         // 64-float small area
    const int blk = blockIdx.x, tid = threadIdx.x;
    const int lane = tid & 31, wrp = tid >> 5;
    const int gid = blk >> 5, gblk = blk & 31;
    const int b0g = gid * 8;

    const int bC = b0g + (gblk >> 2), qC = gblk & 3;   // phase C/D mapping
    const int j0A = gblk * 16;                         // phase A j-slice
    const int n0E = gblk * 16;                         // phase E n-slice

    // ---- one-time weight preload into smem ----
    for (int idx = tid; idx < 32768; idx += NT) {
        int k = idx >> 6, nl = idx & 63;
        int gate = nl >> 4, jj = nl & 15;
        smW[((k >> 2) * 64 + nl) * 4 + (k & 3)] =
            Wh[(size_t)k * G_ + gate * H_ + j0A + jj];
    }
    for (int idx = tid; idx < 16384; idx += NT) {
        int k = idx >> 4, nl = idx & 15;
        smO[((k >> 2) * 16 + nl) * 4 + (k & 3)] =
            Waout[(size_t)k * H_ + n0E + nl];
    }
    __syncthreads();

    for (int t = 0; t < T_; t++) {
        const unsigned t4 = (unsigned)t * 4;

        // ===== A: gates = XG[t] + h@Wh (smem weights), fused LSTM =====
        {
            const float* hp = (t == 0) ? h0 : g_h;
            for (int i = tid; i < 1024; i += NT)
                ((float4*)scr)[i] = ((const float4*)(hp + b0g * H_))[i];
            __syncthreads();
            const int n_loc = tid & 63;
            const int ks = tid >> 6;                   // 8 splits x 64 k
            float acc[8];
#pragma unroll
            for (int i = 0; i < 8; i++) acc[i] = 0.f;
            const float4* w4p = (const float4*)smW + ks * 16 * 64 + n_loc;
#pragma unroll 4
            for (int k4 = 0; k4 < 16; k4++) {
                float4 w4 = w4p[k4 * 64];
#pragma unroll
                for (int b = 0; b < 8; b++) {
                    float4 h4 = ((const float4*)(scr + b * 512))[ks * 16 + k4];
                    acc[b] = fmaf(h4.x, w4.x, fmaf(h4.y, w4.y,
                             fmaf(h4.z, w4.z, fmaf(h4.w, w4.w, acc[b]))));
                }
            }
            __syncthreads();                            // staging reads done
#pragma unroll
            for (int b = 0; b < 8; b++) scr[(ks * 64 + n_loc) * 8 + b] = acc[b];
            __syncthreads();
            {   // 512 threads: one gate value each
                int bb = tid >> 6, g2 = (tid >> 4) & 3, j2 = tid & 15;
                int nl = g2 * 16 + j2;
                float v = 0.f;
#pragma unroll
                for (int s2 = 0; s2 < 8; s2++) v += scr[(s2 * 64 + nl) * 8 + bb];
                v += g_XG[(size_t)(t * B_ + b0g + bb) * G_ + g2 * H_ + j0A + j2];
                scr[4096 + tid] = v;                    // sg[bb][g2][j2]
            }
            __syncthreads();
            if (tid < 128) {
                int bb = tid >> 4, j2 = tid & 15;
                float gi = scr[4096 + bb * 64 + j2];
                float gf = scr[4096 + bb * 64 + 16 + j2];
                float gg = scr[4096 + bb * 64 + 32 + j2];
                float go = scr[4096 + bb * 64 + 48 + j2];
                int b = b0g + bb, j = j0A + j2;
                float cold = (t == 0) ? c0[b * H_ + j] : g_c[b * H_ + j];
                float ig = 1.f / (1.f + expf(-gi));
                float fg = 1.f / (1.f + expf(-gf));
                float g2v = tanhf(gg);
                float og = 1.f / (1.f + expf(-go));
                float cy = fg * cold + ig * g2v;
                float hy = og * tanhf(cy);
                g_c[b * H_ + j] = cy;
                g_cat[b * 2 * H_ + H_ + j] = hy;
            }
        }
        gbar(gid, t4 + 1);

        // ===== B: target = hy @ Wa_in (L2 weights) =====
        {
            const int n0 = gblk * 16;
            for (int i = tid; i < 1024; i += NT) {
                int bb = i >> 7, f = i & 127;
                ((float4*)scr)[i] = ((const float4*)(g_cat + (b0g + bb) * 1024 + 512))[f];
            }
            __syncthreads();
            const int n_loc = tid & 15, ks = tid >> 4;  // 32 splits x 16 k
            float acc[8];
#pragma unroll
            for (int i = 0; i < 8; i++) acc[i] = 0.f;
            const float* wp = Wain + (size_t)(ks * 16) * H_ + n0 + n_loc;
#pragma unroll
            for (int k4 = 0; k4 < 4; k4++) {
                float w0 = wp[(size_t)(k4 * 4 + 0) * H_];
                float w1 = wp[(size_t)(k4 * 4 + 1) * H_];
                float w2 = wp[(size_t)(k4 * 4 + 2) * H_];
                float w3 = wp[(size_t)(k4 * 4 + 3) * H_];
#pragma unroll
                for (int b = 0; b < 8; b++) {
                    float4 h4 = ((const float4*)(scr + b * 512))[ks * 4 + k4];
                    acc[b] = fmaf(h4.x, w0, fmaf(h4.y, w1,
                             fmaf(h4.z, w2, fmaf(h4.w, w3, acc[b]))));
                }
            }
            __syncthreads();                            // staging reads done
#pragma unroll
            for (int b = 0; b < 8; b++) scr[(ks * 16 + n_loc) * 8 + b] = acc[b];
            __syncthreads();
            if (tid < 128) {
                int bb = tid >> 4, nn = tid & 15;
                float v = 0.f;
#pragma unroll
                for (int s2 = 0; s2 < 32; s2++) v += scr[(s2 * 16 + nn) * 8 + bb];
                g_target[(b0g + bb) * H_ + n0 + nn] = v;
            }
        }
        gbar(gid, t4 + 2);

        // ===== C: attention — online softmax, 8 s-rows/warp, ctx from L2 =====
        {
            const int b = bC, q = qC;
            const int sbase = q * 128;
            const float4* tp = (const float4*)(g_target + b * H_);
            float4 tg0 = tp[lane],      tg1 = tp[32 + lane];
            float4 tg2 = tp[64 + lane], tg3 = tp[96 + lane];
            float m = -3.4e38f, z = 0.f;
            float4 a0 = {0,0,0,0}, a1 = a0, a2 = a0, a3 = a0;
#pragma unroll 2
            for (int i = 0; i < 8; i++) {
                int s = sbase + wrp * 8 + i;
                const float4* cr = (const float4*)(ctx + ((size_t)s * B_ + b) * H_);
                float4 c0v = cr[lane],      c1v = cr[32 + lane];
                float4 c2v = cr[64 + lane], c3v = cr[96 + lane];
                float p = c0v.x * tg0.x + c0v.y * tg0.y + c0v.z * tg0.z + c0v.w * tg0.w
                        + c1v.x * tg1.x + c1v.y * tg1.y + c1v.z * tg1.z + c1v.w * tg1.w
                        + c2v.x * tg2.x + c2v.y * tg2.y + c2v.z * tg2.z + c2v.w * tg2.w
                        + c3v.x * tg3.x + c3v.y * tg3.y + c3v.z * tg3.z + c3v.w * tg3.w;
#pragma unroll
                for (int o = 16; o; o >>= 1) p += __shfl_xor_sync(0xffffffffu, p, o);
                if (!lane && outa)
                    outa[(size_t)s * (T_ * B_) + t * B_ + b] = p;   // raw score
                float mn = fmaxf(m, p);
                float sc = expf(m - mn);
                float e  = expf(p - mn);
                z = z * sc + e;
                a0.x = a0.x * sc + e * c0v.x; a0.y = a0.y * sc + e * c0v.y;
                a0.z = a0.z * sc + e * c0v.z; a0.w = a0.w * sc + e * c0v.w;
                a1.x = a1.x * sc + e * c1v.x; a1.y = a1.y * sc + e * c1v.y;
                a1.z = a1.z * sc + e * c1v.z; a1.w = a1.w * sc + e * c1v.w;
                a2.x = a2.x * sc + e * c2v.x; a2.y = a2.y * sc + e * c2v.y;
                a2.z = a2.z * sc + e * c2v.z; a2.w = a2.w * sc + e * c2v.w;
                a3.x = a3.x * sc + e * c3v.x; a3.y = a3.y * sc + e * c3v.y;
                a3.z = a3.z * sc + e * c3v.z; a3.w = a3.w * sc + e * c3v.w;
                m = mn;
            }
            if (!lane) { sml[wrp] = m; sml[16 + wrp] = z; }
            __syncthreads();
            if (wrp == 0) {
                float mw = (lane < 16) ? sml[lane] : -3.4e38f;
                float zw = (lane < 16) ? sml[16 + lane] : 0.f;
                float M = mw;
#pragma unroll
                for (int o = 16; o; o >>= 1)
                    M = fmaxf(M, __shfl_xor_sync(0xffffffffu, M, o));
                float cw = expf(mw - M);
                float Zb = zw * cw;
#pragma unroll
                for (int o = 16; o; o >>= 1) Zb += __shfl_xor_sync(0xffffffffu, Zb, o);
                if (lane < 16) sml[32 + lane] = cw;
                if (!lane) { g_pm[b * 4 + q] = M; g_pz[b * 4 + q] = Zb; }
            }
            __syncthreads();
            float cw = sml[32 + wrp];
            float4* wp4 = (float4*)(scr + wrp * 512);
            float4 s0v = {a0.x*cw, a0.y*cw, a0.z*cw, a0.w*cw};
            float4 s1v = {a1.x*cw, a1.y*cw, a1.z*cw, a1.w*cw};
            float4 s2v = {a2.x*cw, a2.y*cw, a2.z*cw, a2.w*cw};
            float4 s3v = {a3.x*cw, a3.y*cw, a3.z*cw, a3.w*cw};
            wp4[lane] = s0v; wp4[32 + lane] = s1v;
            wp4[64 + lane] = s2v; wp4[96 + lane] = s3v;
            __syncthreads();
            {
                float v = 0.f;
#pragma unroll
                for (int w2 = 0; w2 < 16; w2++) v += scr[w2 * 512 + tid];
                g_pwc[((size_t)b * 4 + q) * H_ + tid] = v;
            }
            __syncthreads();
            if (tid == 0) atom_add_acqrel(&g_bcnt[b], 1u);   // minisync arrive
        }

        // ===== D: wait 4 partials of b, combine -> wc =====
        {
            const int b = bC, q = qC;
            const int k0 = q * 128;
            if (tid == 0) {
                unsigned tgt = 4u * (unsigned)(t + 1);
                while (ld_acq(&g_bcnt[b]) < tgt) { }
            }
            __syncthreads();
            if (wrp == 0) {
                float M4 = (lane < 4) ? g_pm[b * 4 + lane] : -3.4e38f;
                float Z4 = (lane < 4) ? g_pz[b * 4 + lane] : 0.f;
                float M = M4;
#pragma unroll
                for (int o = 16; o; o >>= 1)
                    M = fmaxf(M, __shfl_xor_sync(0xffffffffu, M, o));
                float cc = expf(M4 - M);
                float Z = Z4 * cc;
#pragma unroll
                for (int o = 16; o; o >>= 1) Z += __shfl_xor_sync(0xffffffffu, Z, o);
                if (lane < 4) sml[lane] = cc;
                if (!lane) {
                    sml[4] = 1.f / Z;
                    if (outa) { g_M[t * B_ + b] = M; g_iZ[t * B_ + b] = 1.f / Z; }
                }
            }
            __syncthreads();
            if (tid < 128) {
                int k = k0 + tid;
                float iZ = sml[4];
                float v = 0.f;
#pragma unroll
                for (int c2 = 0; c2 < 4; c2++)
                    v += sml[c2] * g_pwc[((size_t)b * 4 + c2) * H_ + k];
                g_cat[b * 2 * H_ + k] = v * iZ;
            }
        }
        gbar(gid, t4 + 3);

        // ===== E: h = tanh([wc|hy] @ Wa_out) (smem weights), outputs =====
        {
            for (int i = tid; i < 2048; i += NT)
                ((float4*)scr)[i] = ((const float4*)(g_cat + b0g * 1024))[i];
            __syncthreads();
            const int n_loc = tid & 15, ks = tid >> 4;  // 32 splits x 32 k
            float acc[8];
#pragma unroll
            for (int i = 0; i < 8; i++) acc[i] = 0.f;
            const float4* w4p = (const float4*)smO + ks * 8 * 16 + n_loc;
#pragma unroll 4
            for (int k4 = 0; k4 < 8; k4++) {
                float4 w4 = w4p[k4 * 16];
#pragma unroll
                for (int b = 0; b < 8; b++) {
                    float4 h4 = ((const float4*)(scr + b * 1024))[ks * 8 + k4];
                    acc[b] = fmaf(h4.x, w4.x, fmaf(h4.y, w4.y,
                             fmaf(h4.z, w4.z, fmaf(h4.w, w4.w, acc[b]))));
                }
            }
            __syncthreads();                            // staging reads done
#pragma unroll
            for (int b = 0; b < 8; b++) scr[(ks * 16 + n_loc) * 8 + b] = acc[b];
            __syncthreads();
            if (tid < 128) {
                int bb = tid >> 4, nn = tid & 15;
                float v = 0.f;
#pragma unroll
                for (int s2 = 0; s2 < 32; s2++) v += scr[(s2 * 16 + nn) * 8 + bb];
                v = tanhf(v);
                int b = b0g + bb, n = n0E + nn;
                g_h[b * H_ + n] = v;
                if (layer == 0)
                    g_X1[((size_t)t * B_ + b) * H_ + n] = v;
                else
                    outx[(size_t)b * (T_ * H_) + (size_t)t * H_ + n] = v;
                if (t == T_ - 1) {
                    outh[b * H_ + n] = v;
                    outc[b * H_ + n] = g_c[b * H_ + n];
                }
            }
        }
        gbar(gid, t4 + 4);
    }

    // reset group barrier + minisync state for the next launch
    if (tid == 0) {
        unsigned old = atom_add_acqrel(&g_grst[gid], 1u);
        if (old == GSZ - 1) {
            g_grst[gid] = 0;
#pragma unroll
            for (int i = 0; i < 8; i++) g_bcnt[b0g + i] = 0;
            st_rel(&g_ggen[gid], 0u);
        }
    }
}

// ---------------- finalize attention output: in-place softmax ------------------
__global__ void __launch_bounds__(256) k_att(float* __restrict__ outa) {
    const int s = blockIdx.x;
    for (int i = threadIdx.x; i < T_ * B_; i += 256) {
        float v = outa[(size_t)s * (T_ * B_) + i];
        outa[(size_t)s * (T_ * B_) + i] = expf(v - g_M[i]) * g_iZ[i];
    }
}

// ---------------- host orchestration ------------------------------------------
extern "C" void kernel_launch(void* const* d_in, const int* in_sizes, int n_in,
                              void* d_out, int out_size) {
    const float* input = (const float*)d_in[0];
    const float* h0    = (const float*)d_in[1];
    const float* c0    = (const float*)d_in[2];
    const float* ctx   = (const float*)d_in[3];
    const float* Wi    = (const float*)d_in[4];
    const float* bi    = (const float*)d_in[5];
    const float* Wh    = (const float*)d_in[6];
    const float* bh    = (const float*)d_in[7];
    const float* Wain  = (const float*)d_in[8];
    const float* Waout = (const float*)d_in[9];

    float* out  = (float*)d_out;
    float* outx = out;                                   // (B,T,H)
    float* outh = out  + (size_t)B_ * T_ * H_;           // (2,B,H)
    float* outc = outh + 2 * B_ * H_;                    // (2,B,H)
    float* outa = outc + 2 * B_ * H_;                    // (S, T*B)

    const int SMEM = SMEM_FLOATS * 4;  // 229,632 B (opt-in, <= 227 KB limit)
    cudaFuncSetAttribute(k_layer, cudaFuncAttributeMaxDynamicSharedMemorySize, SMEM);

    for (int l = 0; l < 2; l++) {
        const float* Wi_l    = Wi    + (size_t)l * H_ * G_;
        const float* bi_l    = bi    + l * G_;
        const float* Wh_l    = Wh    + (size_t)l * H_ * G_;
        const float* bh_l    = bh    + l * G_;
        const float* Wain_l  = Wain  + (size_t)l * H_ * H_;
        const float* Waout_l = Waout + (size_t)l * 2 * H_ * H_;

        k_pre<<<dim3(G_ / 64, (T_ * B_) / 128), 256>>>(input, Wi_l, bi_l, bh_l, l);
        k_layer<<<NB, NT, SMEM>>>(ctx, Wh_l, Wain_l, Waout_l, h0, c0,
                                  outx, outh + l * B_ * H_, outc + l * B_ * H_,
                                  l == 1 ? outa : nullptr, l);
    }
    k_att<<<S_, 256>>>(outa);
}

// round 11
// speedup vs baseline: 1.5269x; 1.1540x over previous
#include <cuda_runtime.h>
#include <math.h>

#define B_ 32
#define T_ 256
#define S_ 512
#define H_ 512
#define G_ 2048   // 4*H
#define NB 256    // 8 groups x 32 blocks
#define NT 256
#define GSZ 32
#define NGRP 8

// smem floats: [0,16384) Waout slice; [16384,24576) scr; [24576,24640) sml
#define SCR 16384
#define SML 24576
#define SMEM_FLOATS 24640

// ---------------- scratch: __device__ globals (per-layer where needed) --------
__device__ float g_XG[T_ * B_ * G_];       // layer0 pre-gated input (64 MB)
__device__ float g_X1[T_ * B_ * H_];       // layer0 outputs (16 MB)
__device__ float g_h[2 * B_ * H_];
__device__ float g_c[2 * B_ * H_];
__device__ float g_cat[2 * B_ * 2 * H_];   // [wc | hy]
__device__ float g_target[2 * B_ * H_];
__device__ float g_pm[2 * B_ * 4];
__device__ float g_pz[2 * B_ * 4];
__device__ float g_pwc[2 * B_ * 4 * H_];
__device__ float g_M[T_ * B_];             // layer1 softmax max
__device__ float g_iZ[T_ * B_];            // layer1 1/Z

// ---------------- sync state ---------------------------------------------------
__device__ unsigned g_gcnt[NGRP];
__device__ unsigned g_ggen[NGRP];
__device__ unsigned g_grst[NGRP];
__device__ unsigned g_bcnt[2 * B_];        // per-(layer,b) minisync (monotonic)
__device__ unsigned g_p0[4];               // layer0 progress per batch octet

__device__ __forceinline__ unsigned atom_add_acqrel(unsigned* p, unsigned v) {
    unsigned old;
    asm volatile("atom.add.acq_rel.gpu.u32 %0, [%1], %2;"
                 : "=r"(old) : "l"(p), "r"(v) : "memory");
    return old;
}
__device__ __forceinline__ unsigned ld_acq(unsigned* p) {
    unsigned v;
    asm volatile("ld.acquire.gpu.u32 %0, [%1];" : "=r"(v) : "l"(p) : "memory");
    return v;
}
__device__ __forceinline__ void st_rel(unsigned* p, unsigned v) {
    asm volatile("st.release.gpu.u32 [%0], %1;" :: "l"(p), "r"(v) : "memory");
}
__device__ __forceinline__ void gbar(int gid, unsigned target) {
    __syncthreads();
    if (threadIdx.x == 0) {
        unsigned old = atom_add_acqrel(&g_gcnt[gid], 1u);
        if (old == GSZ - 1) {
            g_gcnt[gid] = 0;
            st_rel(&g_ggen[gid], target);
        } else {
            while (ld_acq(&g_ggen[gid]) != target) { }
        }
    }
    __syncthreads();
}

// ---------------- precompute XG = x @ Wi0 + (bi0 + bh0), layer 0 only ---------
__global__ void __launch_bounds__(256) k_pre(const float* __restrict__ Xin,
                                             const float* __restrict__ Wi,
                                             const float* __restrict__ bi,
                                             const float* __restrict__ bh) {
    __shared__ float As[16][128];
    __shared__ float Bs[16][64];
    const int tid = threadIdx.x;
    const int tx = tid & 15, ty = tid >> 4;
    const int n0 = blockIdx.x * 64, m0 = blockIdx.y * 128;
    const int m_l = tid & 127, kb = (tid >> 7) * 8;
    const int m = m0 + m_l;
    const int bb = m & 31, tt = m >> 5;
    const float* arow = Xin + ((size_t)bb * T_ + tt) * H_;
    const int bkk = tid >> 4, bnn = (tid & 15) * 4;

    float acc[8][4];
#pragma unroll
    for (int i = 0; i < 8; i++)
#pragma unroll
        for (int j = 0; j < 4; j++) acc[i][j] = 0.f;

    for (int k0 = 0; k0 < H_; k0 += 16) {
        float4 a0 = *(const float4*)(arow + k0 + kb);
        float4 a1 = *(const float4*)(arow + k0 + kb + 4);
        As[kb + 0][m_l] = a0.x; As[kb + 1][m_l] = a0.y;
        As[kb + 2][m_l] = a0.z; As[kb + 3][m_l] = a0.w;
        As[kb + 4][m_l] = a1.x; As[kb + 5][m_l] = a1.y;
        As[kb + 6][m_l] = a1.z; As[kb + 7][m_l] = a1.w;
        *(float4*)&Bs[bkk][bnn] =
            *(const float4*)(Wi + (size_t)(k0 + bkk) * G_ + n0 + bnn);
        __syncthreads();
#pragma unroll
        for (int kk = 0; kk < 16; kk++) {
            float4 b4  = *(const float4*)&Bs[kk][tx * 4];
            float4 alo = *(const float4*)&As[kk][ty * 8];
            float4 ahi = *(const float4*)&As[kk][ty * 8 + 4];
            float av[8] = {alo.x, alo.y, alo.z, alo.w, ahi.x, ahi.y, ahi.z, ahi.w};
#pragma unroll
            for (int i = 0; i < 8; i++) {
                acc[i][0] = fmaf(av[i], b4.x, acc[i][0]);
                acc[i][1] = fmaf(av[i], b4.y, acc[i][1]);
                acc[i][2] = fmaf(av[i], b4.z, acc[i][2]);
                acc[i][3] = fmaf(av[i], b4.w, acc[i][3]);
            }
        }
        __syncthreads();
    }
    float4 b1 = *(const float4*)(bi + n0 + tx * 4);
    float4 b2 = *(const float4*)(bh + n0 + tx * 4);
    float4 bias = {b1.x + b2.x, b1.y + b2.y, b1.z + b2.z, b1.w + b2.w};
#pragma unroll
    for (int i = 0; i < 8; i++) {
        float4 o = {acc[i][0] + bias.x, acc[i][1] + bias.y,
                    acc[i][2] + bias.z, acc[i][3] + bias.w};
        *(float4*)&g_XG[(size_t)(m0 + ty * 8 + i) * G_ + n0 + tx * 4] = o;
    }
}

// ---------------- persistent wavefront kernel: both layers concurrently -------
__global__ void __launch_bounds__(NT, 2) k_wave(
    const float* __restrict__ ctx,
    const float* __restrict__ Wi,
    const float* __restrict__ bi,
    const float* __restrict__ Wh,
    const float* __restrict__ bh,
    const float* __restrict__ Wain,
    const float* __restrict__ Waout,
    const float* __restrict__ h0,
    const float* __restrict__ c0,
    float* __restrict__ outx,
    float* __restrict__ outh,
    float* __restrict__ outc,
    float* __restrict__ outa)
{
    extern __shared__ float sm[];
    float* smO = sm;            // Waout slice [k 0..1023][n 0..15], float4-over-k
    float* scr = sm + SCR;      // 8192-float stage/reduce overlay
    float* sml = sm + SML;      // 64-float small area
    const int blk = blockIdx.x, tid = threadIdx.x;
    const int lane = tid & 31, wrp = tid >> 5;
    const int gid = blk >> 5, gblk = blk & 31;
    const int lay = gid >> 2, oct = gid & 3;
    const int b0g = oct * 8;

    const int bC = b0g + (gblk >> 2), qC = gblk & 3;   // phase C/D mapping
    const int j0A = gblk * 16;                         // phase A j-slice
    const int n0E = gblk * 16;                         // phase B/E n-slice

    // per-layer weight pointers
    const float* WiL    = Wi    + (size_t)lay * H_ * G_;
    const float* biL    = bi    + lay * G_;
    const float* WhL    = Wh    + (size_t)lay * H_ * G_;
    const float* bhL    = bh    + lay * G_;
    const float* WainL  = Wain  + (size_t)lay * H_ * H_;
    const float* WaoutL = Waout + (size_t)lay * 2 * H_ * H_;

    float* hL   = g_h   + lay * B_ * H_;
    float* cL   = g_c   + lay * B_ * H_;
    float* catL = g_cat + lay * B_ * 2 * H_;
    float* tgtL = g_target + lay * B_ * H_;
    float* pmL  = g_pm  + lay * B_ * 4;
    float* pzL  = g_pz  + lay * B_ * 4;
    float* pwcL = g_pwc + (size_t)lay * B_ * 4 * H_;

    // ---- one-time Waout slice preload ----
    for (int idx = tid; idx < 16384; idx += NT) {
        int k = idx >> 4, nl = idx & 15;
        smO[((k >> 2) * 16 + nl) * 4 + (k & 3)] =
            WaoutL[(size_t)k * H_ + n0E + nl];
    }
    __syncthreads();

    for (int t = 0; t < T_; t++) {
        const unsigned t4 = (unsigned)t * 4;

        // ===== cross-layer gate: layer1 step t needs layer0's X1[t] =====
        if (lay == 1) {
            if (tid == 0) {
                unsigned tgt = (unsigned)(t + 1);
                while (ld_acq(&g_p0[oct]) < tgt) { }
            }
            __syncthreads();
        }

        // ===== A: gates, fused LSTM elementwise =====
        {
            const float* hp = (t == 0) ? (h0) : hL;
            if (lay == 0) {
                for (int i = tid; i < 1024; i += NT)
                    ((float4*)scr)[i] = ((const float4*)(hp + b0g * H_))[i];
            } else {
                const float4* xsrc = (const float4*)(g_X1 + ((size_t)t * B_ + b0g) * H_);
                for (int i = tid; i < 1024; i += NT)
                    ((float4*)scr)[i] = xsrc[i];
                for (int i = tid; i < 1024; i += NT)
                    ((float4*)(scr + 4096))[i] = ((const float4*)(hp + b0g * H_))[i];
            }
            __syncthreads();
            const int n_loc = tid & 63;
            const int ks = tid >> 6;                   // 4 k-splits
            const int n = (n_loc >> 4) * H_ + j0A + (n_loc & 15);
            float acc[8];
#pragma unroll
            for (int i = 0; i < 8; i++) acc[i] = 0.f;
            if (lay == 0) {
                const float* wp = WhL + (size_t)(ks * 128) * G_ + n;
                const float* hb = scr + ks * 128;
#pragma unroll 4
                for (int k4 = 0; k4 < 32; k4++) {
                    float w0 = wp[(size_t)(k4 * 4 + 0) * G_];
                    float w1 = wp[(size_t)(k4 * 4 + 1) * G_];
                    float w2 = wp[(size_t)(k4 * 4 + 2) * G_];
                    float w3 = wp[(size_t)(k4 * 4 + 3) * G_];
#pragma unroll
                    for (int b = 0; b < 8; b++) {
                        float4 h4 = ((const float4*)(hb + b * 512))[k4];
                        acc[b] = fmaf(h4.x, w0, fmaf(h4.y, w1,
                                 fmaf(h4.z, w2, fmaf(h4.w, w3, acc[b]))));
                    }
                }
            } else {
                const float* wp;
                const float* hb;
                if (ks < 2) { wp = WiL + (size_t)(ks * 256) * G_ + n; hb = scr + ks * 256; }
                else        { wp = WhL + (size_t)((ks - 2) * 256) * G_ + n;
                              hb = scr + 4096 + (ks - 2) * 256; }
#pragma unroll 4
                for (int k4 = 0; k4 < 64; k4++) {
                    float w0 = wp[(size_t)(k4 * 4 + 0) * G_];
                    float w1 = wp[(size_t)(k4 * 4 + 1) * G_];
                    float w2 = wp[(size_t)(k4 * 4 + 2) * G_];
                    float w3 = wp[(size_t)(k4 * 4 + 3) * G_];
#pragma unroll
                    for (int b = 0; b < 8; b++) {
                        float4 h4 = ((const float4*)(hb + b * 512))[k4];
                        acc[b] = fmaf(h4.x, w0, fmaf(h4.y, w1,
                                 fmaf(h4.z, w2, fmaf(h4.w, w3, acc[b]))));
                    }
                }
            }
            __syncthreads();                           // staging reads done
#pragma unroll
            for (int b = 0; b < 8; b++) scr[(ks * 64 + n_loc) * 8 + b] = acc[b];
            __syncthreads();
            for (int slot = tid; slot < 512; slot += NT) {
                int bb = slot >> 6, nl = slot & 63;
                int g2 = nl >> 4, j2 = nl & 15;
                float v = scr[nl * 8 + bb] + scr[(64 + nl) * 8 + bb]
                        + scr[(128 + nl) * 8 + bb] + scr[(192 + nl) * 8 + bb];
                if (lay == 0)
                    v += g_XG[(size_t)(t * B_ + b0g + bb) * G_ + g2 * H_ + j0A + j2];
                else
                    v += biL[g2 * H_ + j0A + j2] + bhL[g2 * H_ + j0A + j2];
                scr[4096 + slot] = v;
            }
            __syncthreads();
            if (tid < 128) {
                int bb = tid >> 4, j2 = tid & 15;
                float gi = scr[4096 + bb * 64 + j2];
                float gf = scr[4096 + bb * 64 + 16 + j2];
                float gg = scr[4096 + bb * 64 + 32 + j2];
                float go = scr[4096 + bb * 64 + 48 + j2];
                int b = b0g + bb, j = j0A + j2;
                float cold = (t == 0) ? c0[b * H_ + j] : cL[b * H_ + j];
                float ig = 1.f / (1.f + expf(-gi));
                float fg = 1.f / (1.f + expf(-gf));
                float g2v = tanhf(gg);
                float og = 1.f / (1.f + expf(-go));
                float cy = fg * cold + ig * g2v;
                float hy = og * tanhf(cy);
                cL[b * H_ + j] = cy;
                catL[b * 2 * H_ + H_ + j] = hy;
            }
        }
        gbar(gid, t4 + 1);

        // ===== B: target = hy @ Wa_in =====
        {
            for (int i = tid; i < 1024; i += NT) {
                int bb = i >> 7, f = i & 127;
                ((float4*)scr)[i] = ((const float4*)(catL + (b0g + bb) * 1024 + 512))[f];
            }
            __syncthreads();
            const int n_loc = tid & 15, ks = tid >> 4;  // 16 splits x 32 k
            float acc[8];
#pragma unroll
            for (int i = 0; i < 8; i++) acc[i] = 0.f;
            const float* wp = WainL + (size_t)(ks * 32) * H_ + n0E + n_loc;
            const float* hb = scr + ks * 32;
#pragma unroll 4
            for (int k4 = 0; k4 < 8; k4++) {
                float w0 = wp[(size_t)(k4 * 4 + 0) * H_];
                float w1 = wp[(size_t)(k4 * 4 + 1) * H_];
                float w2 = wp[(size_t)(k4 * 4 + 2) * H_];
                float w3 = wp[(size_t)(k4 * 4 + 3) * H_];
#pragma unroll
                for (int b = 0; b < 8; b++) {
                    float4 h4 = ((const float4*)(hb + b * 512))[k4];
                    acc[b] = fmaf(h4.x, w0, fmaf(h4.y, w1,
                             fmaf(h4.z, w2, fmaf(h4.w, w3, acc[b]))));
                }
            }
            __syncthreads();                           // staging reads done
#pragma unroll
            for (int b = 0; b < 8; b++) scr[(ks * 16 + n_loc) * 8 + b] = acc[b];
            __syncthreads();
            if (tid < 128) {
                int bb = tid >> 4, nn = tid & 15;
                float v = 0.f;
#pragma unroll
                for (int s2 = 0; s2 < 16; s2++) v += scr[(s2 * 16 + nn) * 8 + bb];
                tgtL[(b0g + bb) * H_ + n0E + nn] = v;
            }
        }
        gbar(gid, t4 + 2);

        // ===== C: attention — online softmax, 16 s-rows per warp =====
        {
            const int b = bC, q = qC;
            const int sbase = q * 128;
            const float4* tp = (const float4*)(tgtL + b * H_);
            float4 tg0 = tp[lane],      tg1 = tp[32 + lane];
            float4 tg2 = tp[64 + lane], tg3 = tp[96 + lane];
            float m = -3.4e38f, z = 0.f;
            float4 a0 = {0,0,0,0}, a1 = a0, a2 = a0, a3 = a0;
#pragma unroll 4
            for (int i = 0; i < 16; i++) {
                int s = sbase + wrp * 16 + i;
                const float4* cr = (const float4*)(ctx + ((size_t)s * B_ + b) * H_);
                float4 c0v = cr[lane],      c1v = cr[32 + lane];
                float4 c2v = cr[64 + lane], c3v = cr[96 + lane];
                float p = c0v.x * tg0.x + c0v.y * tg0.y + c0v.z * tg0.z + c0v.w * tg0.w
                        + c1v.x * tg1.x + c1v.y * tg1.y + c1v.z * tg1.z + c1v.w * tg1.w
                        + c2v.x * tg2.x + c2v.y * tg2.y + c2v.z * tg2.z + c2v.w * tg2.w
                        + c3v.x * tg3.x + c3v.y * tg3.y + c3v.z * tg3.z + c3v.w * tg3.w;
#pragma unroll
                for (int o = 16; o; o >>= 1) p += __shfl_xor_sync(0xffffffffu, p, o);
                if (!lane && lay == 1)
                    outa[(size_t)s * (T_ * B_) + t * B_ + b] = p;   // raw score
                float mn = fmaxf(m, p);
                float sc = expf(m - mn);
                float e  = expf(p - mn);
                z = z * sc + e;
                a0.x = a0.x * sc + e * c0v.x; a0.y = a0.y * sc + e * c0v.y;
                a0.z = a0.z * sc + e * c0v.z; a0.w = a0.w * sc + e * c0v.w;
                a1.x = a1.x * sc + e * c1v.x; a1.y = a1.y * sc + e * c1v.y;
                a1.z = a1.z * sc + e * c1v.z; a1.w = a1.w * sc + e * c1v.w;
                a2.x = a2.x * sc + e * c2v.x; a2.y = a2.y * sc + e * c2v.y;
                a2.z = a2.z * sc + e * c2v.z; a2.w = a2.w * sc + e * c2v.w;
                a3.x = a3.x * sc + e * c3v.x; a3.y = a3.y * sc + e * c3v.y;
                a3.z = a3.z * sc + e * c3v.z; a3.w = a3.w * sc + e * c3v.w;
                m = mn;
            }
            if (!lane) { sml[wrp] = m; sml[8 + wrp] = z; }
            __syncthreads();
            if (wrp == 0) {
                float mw = (lane < 8) ? sml[lane] : -3.4e38f;
                float zw = (lane < 8) ? sml[8 + lane] : 0.f;
                float M = mw;
#pragma unroll
                for (int o = 16; o; o >>= 1)
                    M = fmaxf(M, __shfl_xor_sync(0xffffffffu, M, o));
                float cw = expf(mw - M);
                float Zb = zw * cw;
#pragma unroll
                for (int o = 16; o; o >>= 1) Zb += __shfl_xor_sync(0xffffffffu, Zb, o);
                if (lane < 8) sml[16 + lane] = cw;
                if (!lane) { pmL[b * 4 + q] = M; pzL[b * 4 + q] = Zb; }
            }
            __syncthreads();
            float cw = sml[16 + wrp];
            float4* wp4 = (float4*)(scr + wrp * 512);
            float4 s0v = {a0.x*cw, a0.y*cw, a0.z*cw, a0.w*cw};
            float4 s1v = {a1.x*cw, a1.y*cw, a1.z*cw, a1.w*cw};
            float4 s2v = {a2.x*cw, a2.y*cw, a2.z*cw, a2.w*cw};
            float4 s3v = {a3.x*cw, a3.y*cw, a3.z*cw, a3.w*cw};
            wp4[lane] = s0v; wp4[32 + lane] = s1v;
            wp4[64 + lane] = s2v; wp4[96 + lane] = s3v;
            __syncthreads();
            for (int i = tid; i < 512; i += NT) {
                float v = 0.f;
#pragma unroll
                for (int w2 = 0; w2 < 8; w2++) v += scr[w2 * 512 + i];
                pwcL[((size_t)b * 4 + q) * H_ + i] = v;
            }
            __syncthreads();
            if (tid == 0) atom_add_acqrel(&g_bcnt[lay * B_ + b], 1u);
        }

        // ===== D: wait 4 partials of (lay,b), combine -> wc =====
        {
            const int b = bC, q = qC;
            const int k0 = q * 128;
            if (tid == 0) {
                unsigned tgt = 4u * (unsigned)(t + 1);
                while (ld_acq(&g_bcnt[lay * B_ + b]) < tgt) { }
            }
            __syncthreads();
            if (wrp == 0) {
                float M4 = (lane < 4) ? pmL[b * 4 + lane] : -3.4e38f;
                float Z4 = (lane < 4) ? pzL[b * 4 + lane] : 0.f;
                float M = M4;
#pragma unroll
                for (int o = 16; o; o >>= 1)
                    M = fmaxf(M, __shfl_xor_sync(0xffffffffu, M, o));
                float cc = expf(M4 - M);
                float Z = Z4 * cc;
#pragma unroll
                for (int o = 16; o; o >>= 1) Z += __shfl_xor_sync(0xffffffffu, Z, o);
                if (lane < 4) sml[lane] = cc;
                if (!lane) {
                    sml[4] = 1.f / Z;
                    if (lay == 1) { g_M[t * B_ + b] = M; g_iZ[t * B_ + b] = 1.f / Z; }
                }
            }
            __syncthreads();
            if (tid < 128) {
                int k = k0 + tid;
                float iZ = sml[4];
                float v = 0.f;
#pragma unroll
                for (int c2 = 0; c2 < 4; c2++)
                    v += sml[c2] * pwcL[((size_t)b * 4 + c2) * H_ + k];
                catL[b * 2 * H_ + k] = v * iZ;
            }
        }
        gbar(gid, t4 + 3);

        // ===== E: h = tanh([wc|hy] @ Wa_out) (smem weights), outputs =====
        {
            for (int i = tid; i < 2048; i += NT)
                ((float4*)scr)[i] = ((const float4*)(catL + b0g * 1024))[i];
            __syncthreads();
            const int n_loc = tid & 15, ks = tid >> 4;  // 16 splits x 64 k
            float acc[8];
#pragma unroll
            for (int i = 0; i < 8; i++) acc[i] = 0.f;
            const float4* w4p = (const float4*)smO + n_loc;
#pragma unroll 4
            for (int k4 = 0; k4 < 16; k4++) {
                float4 w4 = w4p[(ks * 16 + k4) * 16];
#pragma unroll
                for (int b = 0; b < 8; b++) {
                    float4 h4 = ((const float4*)(scr + b * 1024))[ks * 16 + k4];
                    acc[b] = fmaf(h4.x, w4.x, fmaf(h4.y, w4.y,
                             fmaf(h4.z, w4.z, fmaf(h4.w, w4.w, acc[b]))));
                }
            }
            __syncthreads();                           // staging reads done
#pragma unroll
            for (int b = 0; b < 8; b++) scr[(ks * 16 + n_loc) * 8 + b] = acc[b];
            __syncthreads();
            if (tid < 128) {
                int bb = tid >> 4, nn = tid & 15;
                float v = 0.f;
#pragma unroll
                for (int s2 = 0; s2 < 16; s2++) v += scr[(s2 * 16 + nn) * 8 + bb];
                v = tanhf(v);
                int b = b0g + bb, n = n0E + nn;
                hL[b * H_ + n] = v;
                if (lay == 0)
                    g_X1[((size_t)t * B_ + b) * H_ + n] = v;
                else
                    outx[(size_t)b * (T_ * H_) + (size_t)t * H_ + n] = v;
                if (t == T_ - 1) {
                    outh[lay * B_ * H_ + b * H_ + n] = v;
                    outc[lay * B_ * H_ + b * H_ + n] = cL[b * H_ + n];
                }
            }
        }
        gbar(gid, t4 + 4);

        // layer0 publishes progress for layer1's consumer gate
        if (lay == 0 && gblk == 0 && tid == 0)
            st_rel(&g_p0[oct], (unsigned)(t + 1));
    }

    // reset sync state for next launch
    if (tid == 0) {
        unsigned old = atom_add_acqrel(&g_grst[gid], 1u);
        if (old == GSZ - 1) {
            g_grst[gid] = 0;
#pragma unroll
            for (int i = 0; i < 8; i++) g_bcnt[lay * B_ + b0g + i] = 0;
            if (lay == 1) st_rel(&g_p0[oct], 0u);
            st_rel(&g_ggen[gid], 0u);
        }
    }
}

// ---------------- finalize attention output: normalize raw scores -------------
__global__ void __launch_bounds__(256) k_att(float* __restrict__ outa) {
    const int s = blockIdx.x;
    for (int i = threadIdx.x; i < T_ * B_; i += 256) {
        float v = outa[(size_t)s * (T_ * B_) + i];
        outa[(size_t)s * (T_ * B_) + i] = expf(v - g_M[i]) * g_iZ[i];
    }
}

// ---------------- host orchestration ------------------------------------------
extern "C" void kernel_launch(void* const* d_in, const int* in_sizes, int n_in,
                              void* d_out, int out_size) {
    const float* input = (const float*)d_in[0];
    const float* h0    = (const float*)d_in[1];
    const float* c0    = (const float*)d_in[2];
    const float* ctx   = (const float*)d_in[3];
    const float* Wi    = (const float*)d_in[4];
    const float* bi    = (const float*)d_in[5];
    const float* Wh    = (const float*)d_in[6];
    const float* bh    = (const float*)d_in[7];
    const float* Wain  = (const float*)d_in[8];
    const float* Waout = (const float*)d_in[9];

    float* out  = (float*)d_out;
    float* outx = out;                                   // (B,T,H)
    float* outh = out  + (size_t)B_ * T_ * H_;           // (2,B,H)
    float* outc = outh + 2 * B_ * H_;                    // (2,B,H)
    float* outa = outc + 2 * B_ * H_;                    // (S, T*B)

    const int SMEM = SMEM_FLOATS * 4;  // 98,560 B -> 2 blocks/SM
    cudaFuncSetAttribute(k_wave, cudaFuncAttributeMaxDynamicSharedMemorySize, SMEM);

    k_pre<<<dim3(G_ / 64, (T_ * B_) / 128), 256>>>(input, Wi, bi, bh);
    k_wave<<<NB, NT, SMEM>>>(ctx, Wi, bi, Wh, bh, Wain, Waout, h0, c0,
                             outx, outh, outc, outa);
    k_att<<<S_, 256>>>(outa);
}